// round 1
// baseline (speedup 1.0000x reference)
#include <cuda_runtime.h>
#include <math.h>

#define BB 4
#define TT 256
#define UU 64
#define UP 65          // U+1
#define DJ 512
#define VV 1024
#define MT 64          // lattice rows per joint block
#define NCH 256        // V chunk width
#define KT 16          // K tile depth

// ---------------- scratch (device globals; no allocations allowed) ----------------
__device__ float g_enc_h[BB*TT*DJ];     // 2 MB
__device__ float g_dec_h[BB*UP*DJ];     // 532 KB
__device__ float g_blank[BB*TT*UP];     // 266 KB
__device__ float g_emit [BB*TT*UU];     // 262 KB
__device__ float g_final[BB];

// ---------------- packed f32x2 helpers (Blackwell) ----------------
__device__ __forceinline__ unsigned long long pack2(float lo, float hi) {
    unsigned long long r;
    asm("mov.b64 %0, {%1, %2};" : "=l"(r) : "f"(lo), "f"(hi));
    return r;
}
__device__ __forceinline__ void unpack2(unsigned long long p, float& lo, float& hi) {
    asm("mov.b64 {%0, %1}, %2;" : "=f"(lo), "=f"(hi) : "l"(p));
}
__device__ __forceinline__ void ffma2(unsigned long long& acc, unsigned long long a, unsigned long long b) {
    asm("fma.rn.f32x2 %0, %1, %2, %3;" : "=l"(acc) : "l"(a), "l"(b), "l"(acc));
}

// =====================================================================
// K1/K2: C[M,N] = A[M,K] @ W[N,K]^T + bias[N]   (fp32, small)
// =====================================================================
__global__ void __launch_bounds__(256) gemm_bias_kernel(
    const float* __restrict__ A, const float* __restrict__ W,
    const float* __restrict__ bias, float* __restrict__ C,
    int M, int N, int K)
{
    __shared__ float As[16][64];
    __shared__ float Ws[16][64];
    const int m0 = blockIdx.x * 64;
    const int n0 = blockIdx.y * 64;
    const int tid = threadIdx.x;
    const int tm = tid >> 4;   // 0..15
    const int tn = tid & 15;   // 0..15

    float acc[4][4];
#pragma unroll
    for (int i = 0; i < 4; i++)
#pragma unroll
        for (int j = 0; j < 4; j++) acc[i][j] = 0.f;

    for (int k0 = 0; k0 < K; k0 += 16) {
        __syncthreads();
#pragma unroll
        for (int i = 0; i < 4; i++) {
            int q = tid + i * 256;
            int mm = q >> 4, kk = q & 15;
            int gm = m0 + mm;
            As[kk][mm] = (gm < M) ? A[(size_t)gm * K + k0 + kk] : 0.f;
            int gn = n0 + mm;   // N tiles always full (N=512)
            Ws[kk][mm] = W[(size_t)gn * K + k0 + kk];
        }
        __syncthreads();
#pragma unroll
        for (int kk = 0; kk < 16; kk++) {
            float a[4], w[4];
#pragma unroll
            for (int i = 0; i < 4; i++) a[i] = As[kk][tm * 4 + i];
#pragma unroll
            for (int j = 0; j < 4; j++) w[j] = Ws[kk][tn * 4 + j];
#pragma unroll
            for (int i = 0; i < 4; i++)
#pragma unroll
                for (int j = 0; j < 4; j++) acc[i][j] = fmaf(a[i], w[j], acc[i][j]);
        }
    }
#pragma unroll
    for (int i = 0; i < 4; i++) {
        int gm = m0 + tm * 4 + i;
        if (gm < M) {
#pragma unroll
            for (int j = 0; j < 4; j++) {
                int gn = n0 + tn * 4 + j;
                C[(size_t)gm * N + gn] = acc[i][j] + bias[gn];
            }
        }
    }
}

// =====================================================================
// K3: fused joint GEMM + log-softmax stats.
// One block = 64 lattice rows (b,t,u). h generated on the fly; per row
// we emit blank log-prob and (u<U) emit log-prob. Logits never stored.
// =====================================================================
__global__ void __launch_bounds__(256, 1) joint_kernel(
    const float* __restrict__ Wp, const int* __restrict__ targets)
{
    extern __shared__ float sm[];
    float* hs       = sm;                    // [512][64]  h tile, k-major
    float* wsm      = hs + DJ * MT;          // [16][256]  W_proj k-tile
    float* blanklog = wsm + KT * NCH;        // [64]
    float* tgtlog   = blanklog + MT;         // [64]
    int*   tgtm     = (int*)(tgtlog + MT);   // [64]

    const int tid = threadIdx.x;
    const int tx = tid & 31;   // lane -> v
    const int ty = tid >> 5;   // warp -> owns rows ty*8 .. ty*8+7
    const int g0 = blockIdx.x * MT;

    if (tid < MT) {
        int g = g0 + tid;
        int b = g / (TT * UP);
        int r = g % (TT * UP);
        int u = r % UP;
        tgtm[tid] = (u < UU) ? targets[b * UU + u] : -1;
    }

    // ---- generate h tile: hs[k][m] = tanh(enc_h[b,t,k] * dec_h[b,u,k]) ----
    for (int idx = tid; idx < DJ * MT; idx += 256) {
        int m = idx & (MT - 1);
        int k = idx >> 6;
        int g = g0 + m;
        int b = g / (TT * UP);
        int r = g % (TT * UP);
        int t = r / UP, u = r % UP;
        float e = g_enc_h[((size_t)(b * TT + t)) * DJ + k];
        float d = g_dec_h[((size_t)(b * UP + u)) * DJ + k];
        hs[k * MT + m] = tanhf(e * d);
    }

    float mxr[8], sr[8];
#pragma unroll
    for (int i = 0; i < 8; i++) { mxr[i] = -INFINITY; sr[i] = 0.f; }

#pragma unroll 1
    for (int c = 0; c < VV / NCH; c++) {
        float4 wr[4];
#pragma unroll
        for (int i = 0; i < 4; i++) {
            int q = tid + i * 256;
            int vv = q >> 2, k4 = q & 3;
            wr[i] = *reinterpret_cast<const float4*>(
                &Wp[(size_t)(c * NCH + vv) * DJ + k4 * 4]);
        }

        unsigned long long acc2[8][4];
#pragma unroll
        for (int i = 0; i < 8; i++)
#pragma unroll
            for (int r2 = 0; r2 < 4; r2++) acc2[i][r2] = 0ull;

#pragma unroll 1
        for (int kt = 0; kt < DJ / KT; kt++) {
            __syncthreads();
#pragma unroll
            for (int i = 0; i < 4; i++) {
                int q = tid + i * 256;
                int vv = q >> 2, k4 = q & 3;
                float* ws = &wsm[(k4 * 4) * NCH + vv];
                ws[0 * NCH] = wr[i].x;
                ws[1 * NCH] = wr[i].y;
                ws[2 * NCH] = wr[i].z;
                ws[3 * NCH] = wr[i].w;
            }
            if (kt + 1 < DJ / KT) {
#pragma unroll
                for (int i = 0; i < 4; i++) {
                    int q = tid + i * 256;
                    int vv = q >> 2, k4 = q & 3;
                    wr[i] = *reinterpret_cast<const float4*>(
                        &Wp[(size_t)(c * NCH + vv) * DJ + (kt + 1) * KT + k4 * 4]);
                }
            }
            __syncthreads();

#pragma unroll
            for (int kk = 0; kk < KT; kk++) {
                const float* hrow = &hs[(kt * KT + kk) * MT + ty * 8];
                float4 h0 = *reinterpret_cast<const float4*>(hrow);
                float4 h1 = *reinterpret_cast<const float4*>(hrow + 4);
                unsigned long long hp[8];
                hp[0] = pack2(h0.x, h0.x); hp[1] = pack2(h0.y, h0.y);
                hp[2] = pack2(h0.z, h0.z); hp[3] = pack2(h0.w, h0.w);
                hp[4] = pack2(h1.x, h1.x); hp[5] = pack2(h1.y, h1.y);
                hp[6] = pack2(h1.z, h1.z); hp[7] = pack2(h1.w, h1.w);
#pragma unroll
                for (int r2 = 0; r2 < 4; r2++) {
                    float2 w2 = *reinterpret_cast<const float2*>(
                        &wsm[kk * NCH + tx * 2 + 64 * r2]);
                    unsigned long long wp = pack2(w2.x, w2.y);
#pragma unroll
                    for (int i = 0; i < 8; i++) ffma2(acc2[i][r2], hp[i], wp);
                }
            }
        }

        // ---- epilogue: capture blank/target logits, fold online LSE ----
#pragma unroll
        for (int i = 0; i < 8; i++) {
            float a[8];
#pragma unroll
            for (int r2 = 0; r2 < 4; r2++) unpack2(acc2[i][r2], a[2 * r2], a[2 * r2 + 1]);
            int m = ty * 8 + i;
            int tgt = tgtm[m];
#pragma unroll
            for (int j = 0; j < 8; j++) {
                int v = c * NCH + tx * 2 + 64 * (j >> 1) + (j & 1);
                if (v == 0)   blanklog[m] = a[j];
                if (v == tgt) tgtlog[m]   = a[j];
            }
            float M = a[0];
#pragma unroll
            for (int j = 1; j < 8; j++) M = fmaxf(M, a[j]);
#pragma unroll
            for (int o = 16; o > 0; o >>= 1) M = fmaxf(M, __shfl_xor_sync(0xffffffffu, M, o));
            float S = 0.f;
#pragma unroll
            for (int j = 0; j < 8; j++) S += __expf(a[j] - M);
#pragma unroll
            for (int o = 16; o > 0; o >>= 1) S += __shfl_xor_sync(0xffffffffu, S, o);
            float nm = fmaxf(mxr[i], M);
            sr[i] = sr[i] * __expf(mxr[i] - nm) + S * __expf(M - nm);
            mxr[i] = nm;
        }
        __syncwarp();
    }

    if (tx == 0) {
#pragma unroll
        for (int i = 0; i < 8; i++) {
            int m = ty * 8 + i;
            int g = g0 + m;
            int b = g / (TT * UP);
            int r = g % (TT * UP);
            int t = r / UP, u = r % UP;
            float lse = mxr[i] + __logf(sr[i]);
            g_blank[g] = blanklog[m] - lse;
            if (u < UU) g_emit[(size_t)(b * TT + t) * UU + u] = tgtlog[m] - lse;
        }
    }
}

// =====================================================================
// K4: alpha forward DP (per-batch block; cumulative scans over U+1)
// =====================================================================
__device__ __forceinline__ float lse2(float a, float b) {
    float m = fmaxf(a, b);
    if (m == -INFINITY) return -INFINITY;
    return m + __logf(__expf(a - m) + __expf(b - m));
}

__device__ __forceinline__ float scan_sum(float v, int lane, int wid, float* agg) {
#pragma unroll
    for (int o = 1; o < 32; o <<= 1) {
        float n = __shfl_up_sync(0xffffffffu, v, o);
        if (lane >= o) v += n;
    }
    __syncthreads();
    if (lane == 31) agg[wid] = v;
    __syncthreads();
    float off = 0.f;
    for (int w = 0; w < wid; w++) off += agg[w];
    return v + off;
}

__device__ __forceinline__ float scan_lse(float v, int lane, int wid, float* agg) {
#pragma unroll
    for (int o = 1; o < 32; o <<= 1) {
        float n = __shfl_up_sync(0xffffffffu, v, o);
        if (lane >= o) v = lse2(v, n);
    }
    __syncthreads();
    if (lane == 31) agg[wid] = v;
    __syncthreads();
    float off = -INFINITY;
    for (int w = 0; w < wid; w++) off = lse2(off, agg[w]);
    return lse2(v, off);
}

__global__ void dp_kernel(const int* __restrict__ in_len, const int* __restrict__ tgt_len) {
    const int b = blockIdx.x;
    const int tid = threadIdx.x;
    const int lane = tid & 31, wid = tid >> 5;
    __shared__ float agg[4];

    const float* blank = g_blank + (size_t)b * TT * UP;
    const float* emit  = g_emit  + (size_t)b * TT * UU;
    const int til = in_len[b];
    const int ul  = tgt_len[b];
    const bool act = tid < UP;

    // alpha0[u] = exclusive cumsum of emit[0,:]
    float x = (tid >= 1 && tid < UP) ? emit[tid - 1] : 0.f;
    float cem = scan_sum(x, lane, wid, agg);
    float alpha = act ? cem : -INFINITY;

    for (int t = 1; t < til; t++) {
        float tmp = act ? (alpha + blank[(size_t)(t - 1) * UP + tid]) : -INFINITY;
        float xe = (tid >= 1 && tid < UP) ? emit[(size_t)t * UU + tid - 1] : 0.f;
        float ce = scan_sum(xe, lane, wid, agg);
        float y = act ? (tmp - ce) : -INFINITY;
        y = scan_lse(y, lane, wid, agg);
        alpha = act ? (y + ce) : -INFINITY;
    }
    if (tid == ul) g_final[b] = alpha + blank[(size_t)(til - 1) * UP + ul];
}

__global__ void finalize_kernel(float* out) {
    out[0] = -0.25f * (g_final[0] + g_final[1] + g_final[2] + g_final[3]);
}

// =====================================================================
// launch
// =====================================================================
extern "C" void kernel_launch(void* const* d_in, const int* in_sizes, int n_in,
                              void* d_out, int out_size)
{
    const float* enc     = (const float*)d_in[0];
    const float* dec     = (const float*)d_in[1];
    const int*   targets = (const int*)  d_in[2];
    const int*   in_len  = (const int*)  d_in[3];
    const int*   tgt_len = (const int*)  d_in[4];
    const float* W_enc   = (const float*)d_in[5];
    const float* b_enc   = (const float*)d_in[6];
    const float* W_dec   = (const float*)d_in[7];
    const float* b_dec   = (const float*)d_in[8];
    const float* W_proj  = (const float*)d_in[9];

    void *pe = nullptr, *pd = nullptr;
    cudaGetSymbolAddress(&pe, g_enc_h);
    cudaGetSymbolAddress(&pd, g_dec_h);

    const int smem_joint = (DJ * MT + KT * NCH + 2 * MT) * (int)sizeof(float) + MT * (int)sizeof(int);
    cudaFuncSetAttribute(joint_kernel, cudaFuncAttributeMaxDynamicSharedMemorySize, smem_joint);

    dim3 g1((BB * TT + 63) / 64, DJ / 64);
    gemm_bias_kernel<<<g1, 256>>>(enc, W_enc, b_enc, (float*)pe, BB * TT, DJ, 512);

    dim3 g2((BB * UP + 63) / 64, DJ / 64);
    gemm_bias_kernel<<<g2, 256>>>(dec, W_dec, b_dec, (float*)pd, BB * UP, DJ, 512);

    joint_kernel<<<(BB * TT * UP) / MT, 256, smem_joint>>>(W_proj, targets);

    dp_kernel<<<BB, 128>>>(in_len, tgt_len);

    finalize_kernel<<<1, 1>>>((float*)d_out);
}

// round 3
// speedup vs baseline: 3.4325x; 3.4325x over previous
#include <cuda_runtime.h>
#include <cuda_bf16.h>
#include <math.h>
#include <stdint.h>

#define BB 4
#define TT 256
#define UU 64
#define UP 65          // U+1
#define DJ 512
#define VV 1024
#define MTILE 128      // lattice rows per joint CTA
#define A_BYTES (MTILE*DJ*2)     // 131072: h tile bf16, XOR-swizzled rows
#define B_ROW_BYTES 80           // 64B data + 16B pad (conflict-free ldmatrix)
#define BT_BYTES (128*B_ROW_BYTES)
#define NBUF 3

// ---------------- scratch ----------------
__device__ float g_enc_h[BB*TT*DJ];
__device__ float g_dec_h[BB*UP*DJ];
__device__ float g_blank[BB*TT*UP];
__device__ float g_emit [BB*TT*UU];
__device__ float g_final[BB];
__device__ __nv_bfloat16 g_wp[VV*DJ];   // W_proj bf16 [V][K] row-major

// ---------------- helpers ----------------
__device__ __forceinline__ uint32_t smem_u32(const void* p) {
    uint32_t a;
    asm("{ .reg .u64 t; cvta.to.shared.u64 t, %1; cvt.u32.u64 %0, t; }" : "=r"(a) : "l"(p));
    return a;
}
__device__ __forceinline__ float tanh_fast(float x) {
    float r; asm("tanh.approx.f32 %0, %1;" : "=f"(r) : "f"(x)); return r;
}
__device__ __forceinline__ uint32_t pack_bf16x2(float lo, float hi) {
    uint32_t r; asm("cvt.rn.bf16x2.f32 %0, %1, %2;" : "=r"(r) : "f"(hi), "f"(lo)); return r;
}
__device__ __forceinline__ void cp_async16(uint32_t dst, const void* src) {
    asm volatile("cp.async.cg.shared.global [%0], [%1], 16;\n" :: "r"(dst), "l"(src) : "memory");
}
__device__ __forceinline__ void ldsm_x4(uint32_t (&r)[4], uint32_t addr) {
    asm volatile("ldmatrix.sync.aligned.m8n8.x4.shared.b16 {%0,%1,%2,%3}, [%4];"
                 : "=r"(r[0]), "=r"(r[1]), "=r"(r[2]), "=r"(r[3]) : "r"(addr));
}
__device__ __forceinline__ void mma_bf16(float (&c)[4], const uint32_t (&a)[4],
                                         uint32_t b0, uint32_t b1) {
    asm volatile(
        "mma.sync.aligned.m16n8k16.row.col.f32.bf16.bf16.f32 "
        "{%0,%1,%2,%3}, {%4,%5,%6,%7}, {%8,%9}, {%0,%1,%2,%3};"
        : "+f"(c[0]), "+f"(c[1]), "+f"(c[2]), "+f"(c[3])
        : "r"(a[0]), "r"(a[1]), "r"(a[2]), "r"(a[3]), "r"(b0), "r"(b1));
}

// =====================================================================
// K0: W_proj fp32 -> bf16
// =====================================================================
__global__ void convert_wp_kernel(const float* __restrict__ Wp) {
    int idx = blockIdx.x * 256 + threadIdx.x;
    g_wp[idx] = __float2bfloat16(Wp[idx]);
}

// =====================================================================
// K1/K2: C[M,N] = A[M,K] @ W[N,K]^T + bias[N]
// =====================================================================
__global__ void __launch_bounds__(256) gemm_bias_kernel(
    const float* __restrict__ A, const float* __restrict__ W,
    const float* __restrict__ bias, float* __restrict__ C,
    int M, int N, int K)
{
    __shared__ float As[16][64];
    __shared__ float Ws[16][64];
    const int m0 = blockIdx.x * 64;
    const int n0 = blockIdx.y * 64;
    const int tid = threadIdx.x;
    const int tm = tid >> 4, tn = tid & 15;

    float acc[4][4];
#pragma unroll
    for (int i = 0; i < 4; i++)
#pragma unroll
        for (int j = 0; j < 4; j++) acc[i][j] = 0.f;

    for (int k0 = 0; k0 < K; k0 += 16) {
        __syncthreads();
#pragma unroll
        for (int i = 0; i < 4; i++) {
            int q = tid + i * 256;
            int mm = q >> 4, kk = q & 15;
            int gm = m0 + mm;
            As[kk][mm] = (gm < M) ? A[(size_t)gm * K + k0 + kk] : 0.f;
            int gn = n0 + mm;
            Ws[kk][mm] = W[(size_t)gn * K + k0 + kk];
        }
        __syncthreads();
#pragma unroll
        for (int kk = 0; kk < 16; kk++) {
            float a[4], w[4];
#pragma unroll
            for (int i = 0; i < 4; i++) a[i] = As[kk][tm * 4 + i];
#pragma unroll
            for (int j = 0; j < 4; j++) w[j] = Ws[kk][tn * 4 + j];
#pragma unroll
            for (int i = 0; i < 4; i++)
#pragma unroll
                for (int j = 0; j < 4; j++) acc[i][j] = fmaf(a[i], w[j], acc[i][j]);
        }
    }
#pragma unroll
    for (int i = 0; i < 4; i++) {
        int gm = m0 + tm * 4 + i;
        if (gm < M) {
#pragma unroll
            for (int j = 0; j < 4; j++) {
                int gn = n0 + tn * 4 + j;
                C[(size_t)gm * N + gn] = acc[i][j] + bias[gn];
            }
        }
    }
}

// =====================================================================
// K3: mma.sync bf16 joint GEMM + fused log-softmax stats
// =====================================================================
__device__ __forceinline__ void load_b_tile(int nc, int kt, uint32_t b_base, int tid) {
    uint32_t buf = b_base + (uint32_t)(kt % NBUF) * BT_BYTES;
    int idx0 = tid * 2;
#pragma unroll
    for (int i = 0; i < 2; i++) {
        int idx = idx0 + i;
        int n = idx >> 2, ch = idx & 3;
        uint32_t dst = buf + (uint32_t)(n * B_ROW_BYTES) + ((uint32_t)ch << 4);
        const __nv_bfloat16* src = g_wp + ((size_t)(nc * 128 + n) * DJ + kt * 32 + ch * 8);
        cp_async16(dst, src);
    }
    asm volatile("cp.async.commit_group;" ::: "memory");
}

__global__ void __launch_bounds__(256, 1) joint_kernel(const int* __restrict__ targets)
{
    extern __shared__ __align__(16) char dyn[];
    __shared__ int   tgtm[MTILE];
    __shared__ float smx[2][MTILE], ssm[2][MTILE], stgt[2][MTILE], sblank[MTILE];

    const uint32_t base = (smem_u32(dyn) + 1023u) & ~1023u;
    const uint32_t a_base = base;
    const uint32_t b_base = base + A_BYTES;

    const int tid  = threadIdx.x;
    const int lane = tid & 31;
    const int wid  = tid >> 5;
    const int warp_m = wid & 3;     // 4 M-warps of 32 rows
    const int warp_n = wid >> 2;    // 2 N-warps of 64 cols
    const int g0 = blockIdx.x * MTILE;
    const unsigned FM = 0xffffffffu;

    if (tid < MTILE) {
        int g = g0 + tid;
        int b = g / (TT * UP);
        int r = g - b * (TT * UP);
        int u = r % UP;
        tgtm[tid] = (u < UU) ? targets[b * UU + u] : -1;
    }

    // ---- generate h tile into XOR-swizzled A (bf16) ----
    {
        const int m = tid >> 1;
        const int khalf = (tid & 1) * 256;
        int g = g0 + m;
        int b = g / (TT * UP);
        int r = g - b * (TT * UP);
        int t = r / UP, u = r - t * UP;
        const float4* er = reinterpret_cast<const float4*>(
            g_enc_h + ((size_t)(b * TT + t)) * DJ + khalf);
        const float4* dr = reinterpret_cast<const float4*>(
            g_dec_h + ((size_t)(b * UP + u)) * DJ + khalf);
        const uint32_t mrow = a_base + (uint32_t)m * 1024u;
        const uint32_t msw = (uint32_t)(m & 7);
#pragma unroll 4
        for (int i = 0; i < 32; i++) {
            int k = khalf + i * 8;
            float4 e0 = er[i * 2], e1 = er[i * 2 + 1];
            float4 d0 = dr[i * 2], d1 = dr[i * 2 + 1];
            uint32_t p0 = pack_bf16x2(tanh_fast(e0.x * d0.x), tanh_fast(e0.y * d0.y));
            uint32_t p1 = pack_bf16x2(tanh_fast(e0.z * d0.z), tanh_fast(e0.w * d0.w));
            uint32_t p2 = pack_bf16x2(tanh_fast(e1.x * d1.x), tanh_fast(e1.y * d1.y));
            uint32_t p3 = pack_bf16x2(tanh_fast(e1.z * d1.z), tanh_fast(e1.w * d1.w));
            uint32_t c = (uint32_t)(k >> 3);
            uint32_t addr = mrow + ((c ^ msw) << 4);
            asm volatile("st.shared.v4.b32 [%0], {%1,%2,%3,%4};"
                         :: "r"(addr), "r"(p0), "r"(p1), "r"(p2), "r"(p3) : "memory");
        }
    }
    __syncthreads();

    // ---- per-lane ldmatrix base addresses ----
    const int rowA = warp_m * 32 + (lane & 15);
    const uint32_t a_lane = a_base + (uint32_t)rowA * 1024u;
    const uint32_t swzA = (uint32_t)(rowA & 7);
    const uint32_t cbaseA = (uint32_t)(lane >> 4);
    const uint32_t b_lane_off =
        (uint32_t)((warp_n * 64 + ((lane >> 4) << 3) + (lane & 7)) * B_ROW_BYTES)
        + ((uint32_t)((lane >> 3) & 1) << 4);

    // ---- per-row epilogue state ----
    float mx[4], sm[4], blankv[4], tgtv[4];
    int tg[4];
#pragma unroll
    for (int g = 0; g < 4; g++) {
        mx[g] = -1e30f; sm[g] = 0.f; blankv[g] = 0.f; tgtv[g] = 0.f;
        int m = warp_m * 32 + (g >> 1) * 16 + (g & 1) * 8 + (lane >> 2);
        tg[g] = tgtm[m];
    }

#pragma unroll 1
    for (int nc = 0; nc < 8; nc++) {
        __syncthreads();   // all warps done with B buffers from previous nc
        load_b_tile(nc, 0, b_base, tid);
        load_b_tile(nc, 1, b_base, tid);

        float acc[2][8][4];
#pragma unroll
        for (int mi = 0; mi < 2; mi++)
#pragma unroll
            for (int nf = 0; nf < 8; nf++)
#pragma unroll
                for (int j = 0; j < 4; j++) acc[mi][nf][j] = 0.f;

#pragma unroll 1
        for (int kt = 0; kt < 16; kt++) {
            if (kt < 15) asm volatile("cp.async.wait_group 1;" ::: "memory");
            else         asm volatile("cp.async.wait_group 0;" ::: "memory");
            __syncthreads();
            if (kt + 2 < 16) load_b_tile(nc, kt + 2, b_base, tid);

            const uint32_t bbuf = b_base + (uint32_t)(kt % NBUF) * BT_BYTES;
#pragma unroll
            for (int k16 = 0; k16 < 2; k16++) {
                uint32_t a0[4], a1[4];
                uint32_t c = (uint32_t)(kt * 4 + k16 * 2) + cbaseA;
                uint32_t aaddr = a_lane + ((c ^ swzA) << 4);
                ldsm_x4(a0, aaddr);
                ldsm_x4(a1, aaddr + 16384u);
                uint32_t b[4][4];
#pragma unroll
                for (int p = 0; p < 4; p++) {
                    uint32_t baddr = bbuf + b_lane_off + (uint32_t)(p * 16 * B_ROW_BYTES)
                                   + ((uint32_t)k16 << 5);
                    ldsm_x4(b[p], baddr);
                }
#pragma unroll
                for (int p = 0; p < 4; p++) {
                    mma_bf16(acc[0][2 * p],     a0, b[p][0], b[p][1]);
                    mma_bf16(acc[0][2 * p + 1], a0, b[p][2], b[p][3]);
                    mma_bf16(acc[1][2 * p],     a1, b[p][0], b[p][1]);
                    mma_bf16(acc[1][2 * p + 1], a1, b[p][2], b[p][3]);
                }
            }
        }

        // ---- epilogue: fold this 128-col chunk into online LSE state ----
        const int vbase = nc * 128 + warp_n * 64 + (lane & 3) * 2;
#pragma unroll
        for (int g = 0; g < 4; g++) {
            const int mi = g >> 1, hf = (g & 1) * 2;
            float lm = -1e30f;
#pragma unroll
            for (int nf = 0; nf < 8; nf++)
                lm = fmaxf(lm, fmaxf(acc[mi][nf][hf], acc[mi][nf][hf + 1]));
            lm = fmaxf(lm, __shfl_xor_sync(FM, lm, 1));
            lm = fmaxf(lm, __shfl_xor_sync(FM, lm, 2));
            float ls = 0.f;
#pragma unroll
            for (int nf = 0; nf < 8; nf++)
                ls += __expf(acc[mi][nf][hf] - lm) + __expf(acc[mi][nf][hf + 1] - lm);
            ls += __shfl_xor_sync(FM, ls, 1);
            ls += __shfl_xor_sync(FM, ls, 2);
            float nm = fmaxf(mx[g], lm);
            sm[g] = sm[g] * __expf(mx[g] - nm) + ls * __expf(lm - nm);
            mx[g] = nm;
#pragma unroll
            for (int nf = 0; nf < 8; nf++) {
                int v0 = vbase + nf * 8;
                if (v0 == 0)          blankv[g] = acc[mi][nf][hf];
                if (v0 == tg[g])      tgtv[g]   = acc[mi][nf][hf];
                if (v0 + 1 == tg[g])  tgtv[g]   = acc[mi][nf][hf + 1];
            }
        }
    }

    // gather captured values across the 4 lanes of each row group
#pragma unroll
    for (int g = 0; g < 4; g++) {
        tgtv[g]  += __shfl_xor_sync(FM, tgtv[g], 1);
        tgtv[g]  += __shfl_xor_sync(FM, tgtv[g], 2);
        blankv[g] += __shfl_xor_sync(FM, blankv[g], 1);
        blankv[g] += __shfl_xor_sync(FM, blankv[g], 2);
    }

    if ((lane & 3) == 0) {
#pragma unroll
        for (int g = 0; g < 4; g++) {
            int m = warp_m * 32 + (g >> 1) * 16 + (g & 1) * 8 + (lane >> 2);
            smx[warp_n][m] = mx[g];
            ssm[warp_n][m] = sm[g];
            stgt[warp_n][m] = tgtv[g];
            if (warp_n == 0) sblank[m] = blankv[g];
        }
    }
    __syncthreads();

    if (tid < MTILE) {
        int m = tid;
        float m0 = smx[0][m], m1 = smx[1][m];
        float nm = fmaxf(m0, m1);
        float s = ssm[0][m] * __expf(m0 - nm) + ssm[1][m] * __expf(m1 - nm);
        float lse = nm + __logf(s);
        int g = g0 + m;
        int b = g / (TT * UP);
        int r = g - b * (TT * UP);
        int t = r / UP, u = r - t * UP;
        g_blank[g] = sblank[m] - lse;
        if (u < UU) {
            int h = (tgtm[m] >> 6) & 1;
            g_emit[(size_t)(b * TT + t) * UU + u] = stgt[h][m] - lse;
        }
    }
}

// =====================================================================
// K4: alpha DP — one warp per batch, 3 u per lane, (m,s)-pair LSE scan
// =====================================================================
__global__ void dp_kernel(const int* __restrict__ in_len, const int* __restrict__ tgt_len) {
    const int b = blockIdx.x;
    const int lane = threadIdx.x;
    const float* blank = g_blank + (size_t)b * TT * UP;
    const float* emit  = g_emit  + (size_t)b * TT * UU;
    const int til = in_len[b];
    const int ul  = tgt_len[b];
    const int u0 = lane * 3;
    const unsigned FM = 0xffffffffu;

    float alpha[3];

    {
        float x0 = (u0 >= 1 && u0 < UP) ? emit[u0 - 1] : 0.f;
        float x1 = (u0 + 1 < UP) ? emit[u0] : 0.f;
        float x2 = (u0 + 2 < UP) ? emit[u0 + 1] : 0.f;
        float s0 = x0, s1 = s0 + x1, s2 = s1 + x2;
        float tot = s2;
#pragma unroll
        for (int o = 1; o < 32; o <<= 1) {
            float n = __shfl_up_sync(FM, tot, o);
            if (lane >= o) tot += n;
        }
        float ex = __shfl_up_sync(FM, tot, 1);
        if (lane == 0) ex = 0.f;
        alpha[0] = ex + s0; alpha[1] = ex + s1; alpha[2] = ex + s2;
    }

    float bl[3], xe[3];
    {
        const float* bp = blank;
        bl[0] = (u0 < UP) ? bp[u0] : 0.f;
        bl[1] = (u0 + 1 < UP) ? bp[u0 + 1] : 0.f;
        bl[2] = (u0 + 2 < UP) ? bp[u0 + 2] : 0.f;
        const float* ep = emit + UU;
        xe[0] = (u0 >= 1 && u0 < UP) ? ep[u0 - 1] : 0.f;
        xe[1] = (u0 + 1 < UP) ? ep[u0] : 0.f;
        xe[2] = (u0 + 2 < UP) ? ep[u0 + 1] : 0.f;
    }

    for (int t = 1; t < til; t++) {
        float nbl[3], nxe[3];
        if (t + 1 < til) {
            const float* bp = blank + (size_t)t * UP;
            nbl[0] = (u0 < UP) ? bp[u0] : 0.f;
            nbl[1] = (u0 + 1 < UP) ? bp[u0 + 1] : 0.f;
            nbl[2] = (u0 + 2 < UP) ? bp[u0 + 2] : 0.f;
            const float* ep = emit + (size_t)(t + 1) * UU;
            nxe[0] = (u0 >= 1 && u0 < UP) ? ep[u0 - 1] : 0.f;
            nxe[1] = (u0 + 1 < UP) ? ep[u0] : 0.f;
            nxe[2] = (u0 + 2 < UP) ? ep[u0 + 1] : 0.f;
        }

        float ce[3];
        {
            float s0 = xe[0], s1 = s0 + xe[1], s2 = s1 + xe[2];
            float tot = s2;
#pragma unroll
            for (int o = 1; o < 32; o <<= 1) {
                float n = __shfl_up_sync(FM, tot, o);
                if (lane >= o) tot += n;
            }
            float ex = __shfl_up_sync(FM, tot, 1);
            if (lane == 0) ex = 0.f;
            ce[0] = ex + s0; ce[1] = ex + s1; ce[2] = ex + s2;
        }

        float x0 = (u0 < UP)     ? (alpha[0] + bl[0] - ce[0]) : -1e30f;
        float x1 = (u0 + 1 < UP) ? (alpha[1] + bl[1] - ce[1]) : -1e30f;
        float x2 = (u0 + 2 < UP) ? (alpha[2] + bl[2] - ce[2]) : -1e30f;

        float m0 = x0, s0 = 1.f;
        float m1 = fmaxf(m0, x1);
        float s1 = s0 * __expf(m0 - m1) + __expf(x1 - m1);
        float m2 = fmaxf(m1, x2);
        float s2 = s1 * __expf(m1 - m2) + __expf(x2 - m2);

        float Mt = m2, St = s2;
#pragma unroll
        for (int o = 1; o < 32; o <<= 1) {
            float mo = __shfl_up_sync(FM, Mt, o);
            float so = __shfl_up_sync(FM, St, o);
            if (lane >= o) {
                float nm = fmaxf(Mt, mo);
                St = so * __expf(mo - nm) + St * __expf(Mt - nm);
                Mt = nm;
            }
        }
        float Me = __shfl_up_sync(FM, Mt, 1);
        float Se = __shfl_up_sync(FM, St, 1);
        if (lane == 0) { Me = -1e30f; Se = 0.f; }

        {
            float nm = fmaxf(Me, m0);
            float S = Se * __expf(Me - nm) + s0 * __expf(m0 - nm);
            alpha[0] = nm + __logf(S) + ce[0];
        }
        {
            float nm = fmaxf(Me, m1);
            float S = Se * __expf(Me - nm) + s1 * __expf(m1 - nm);
            alpha[1] = nm + __logf(S) + ce[1];
        }
        {
            float nm = fmaxf(Me, m2);
            float S = Se * __expf(Me - nm) + s2 * __expf(m2 - nm);
            alpha[2] = nm + __logf(S) + ce[2];
        }

        bl[0] = nbl[0]; bl[1] = nbl[1]; bl[2] = nbl[2];
        xe[0] = nxe[0]; xe[1] = nxe[1]; xe[2] = nxe[2];
    }

    int j = ul - u0;
    if (j >= 0 && j < 3) {
        float a = (j == 0) ? alpha[0] : (j == 1) ? alpha[1] : alpha[2];
        g_final[b] = a + blank[(size_t)(til - 1) * UP + ul];
    }
}

__global__ void finalize_kernel(float* out) {
    out[0] = -0.25f * (g_final[0] + g_final[1] + g_final[2] + g_final[3]);
}

// =====================================================================
// launch
// =====================================================================
extern "C" void kernel_launch(void* const* d_in, const int* in_sizes, int n_in,
                              void* d_out, int out_size)
{
    const float* enc     = (const float*)d_in[0];
    const float* dec     = (const float*)d_in[1];
    const int*   targets = (const int*)  d_in[2];
    const int*   in_len  = (const int*)  d_in[3];
    const int*   tgt_len = (const int*)  d_in[4];
    const float* W_enc   = (const float*)d_in[5];
    const float* b_enc   = (const float*)d_in[6];
    const float* W_dec   = (const float*)d_in[7];
    const float* b_dec   = (const float*)d_in[8];
    const float* W_proj  = (const float*)d_in[9];

    void *pe = nullptr, *pd = nullptr;
    cudaGetSymbolAddress(&pe, g_enc_h);
    cudaGetSymbolAddress(&pd, g_dec_h);

    const int smem_joint = 1024 + A_BYTES + NBUF * BT_BYTES;   // 162 KB
    cudaFuncSetAttribute(joint_kernel, cudaFuncAttributeMaxDynamicSharedMemorySize, smem_joint);

    convert_wp_kernel<<<(VV * DJ) / 256, 256>>>(W_proj);

    dim3 g1((BB * TT + 63) / 64, DJ / 64);
    gemm_bias_kernel<<<g1, 256>>>(enc, W_enc, b_enc, (float*)pe, BB * TT, DJ, 512);

    dim3 g2((BB * UP + 63) / 64, DJ / 64);
    gemm_bias_kernel<<<g2, 256>>>(dec, W_dec, b_dec, (float*)pd, BB * UP, DJ, 512);

    joint_kernel<<<(BB * TT * UP) / MTILE, 256, smem_joint>>>(targets);

    dp_kernel<<<BB, 32>>>(in_len, tgt_len);

    finalize_kernel<<<1, 1>>>((float*)d_out);
}

// round 4
// speedup vs baseline: 3.4887x; 1.0164x over previous
#include <cuda_runtime.h>
#include <cuda_bf16.h>
#include <math.h>
#include <stdint.h>

#define BB 4
#define TT 256
#define UU 64
#define UP 65          // U+1
#define DJ 512
#define VV 1024
#define MTILE 128      // lattice rows per joint CTA
#define A_BYTES (MTILE*DJ*2)     // 131072
#define BT_BYTES (128*256)       // 32768: 128n x 128k bf16, XOR-swizzled 256B rows
#define NBUF 3
#define NTILES 32                // 8 nc x 4 ktile

// ---------------- scratch ----------------
__device__ float g_enc_h[BB*TT*DJ];
__device__ float g_dec_h[BB*UP*DJ];
__device__ float g_blank[BB*TT*UP];
__device__ float g_emit [BB*TT*UU];
__device__ float g_final[BB];
__device__ __nv_bfloat16 g_wp[VV*DJ];   // W_proj bf16 [V][K] row-major

// ---------------- helpers ----------------
__device__ __forceinline__ uint32_t smem_u32(const void* p) {
    uint32_t a;
    asm("{ .reg .u64 t; cvta.to.shared.u64 t, %1; cvt.u32.u64 %0, t; }" : "=r"(a) : "l"(p));
    return a;
}
__device__ __forceinline__ float tanh_fast(float x) {
    float r; asm("tanh.approx.f32 %0, %1;" : "=f"(r) : "f"(x)); return r;
}
__device__ __forceinline__ uint32_t pack_bf16x2(float lo, float hi) {
    uint32_t r; asm("cvt.rn.bf16x2.f32 %0, %1, %2;" : "=r"(r) : "f"(hi), "f"(lo)); return r;
}
__device__ __forceinline__ void cp_async16(uint32_t dst, const void* src) {
    asm volatile("cp.async.cg.shared.global [%0], [%1], 16;\n" :: "r"(dst), "l"(src) : "memory");
}
__device__ __forceinline__ void ldsm_x4(uint32_t (&r)[4], uint32_t addr) {
    asm volatile("ldmatrix.sync.aligned.m8n8.x4.shared.b16 {%0,%1,%2,%3}, [%4];"
                 : "=r"(r[0]), "=r"(r[1]), "=r"(r[2]), "=r"(r[3]) : "r"(addr));
}
__device__ __forceinline__ void mma_bf16(float (&c)[4], const uint32_t (&a)[4],
                                         uint32_t b0, uint32_t b1) {
    asm volatile(
        "mma.sync.aligned.m16n8k16.row.col.f32.bf16.bf16.f32 "
        "{%0,%1,%2,%3}, {%4,%5,%6,%7}, {%8,%9}, {%0,%1,%2,%3};"
        : "+f"(c[0]), "+f"(c[1]), "+f"(c[2]), "+f"(c[3])
        : "r"(a[0]), "r"(a[1]), "r"(a[2]), "r"(a[3]), "r"(b0), "r"(b1));
}

// =====================================================================
// K0: W_proj fp32 -> bf16
// =====================================================================
__global__ void convert_wp_kernel(const float* __restrict__ Wp) {
    int idx = blockIdx.x * 256 + threadIdx.x;
    g_wp[idx] = __float2bfloat16(Wp[idx]);
}

// =====================================================================
// K1/K2: C[M,N] = A[M,K] @ W[N,K]^T + bias[N]
// =====================================================================
__global__ void __launch_bounds__(256) gemm_bias_kernel(
    const float* __restrict__ A, const float* __restrict__ W,
    const float* __restrict__ bias, float* __restrict__ C,
    int M, int N, int K)
{
    __shared__ float As[16][64];
    __shared__ float Ws[16][64];
    const int m0 = blockIdx.x * 64;
    const int n0 = blockIdx.y * 64;
    const int tid = threadIdx.x;
    const int tm = tid >> 4, tn = tid & 15;

    float acc[4][4];
#pragma unroll
    for (int i = 0; i < 4; i++)
#pragma unroll
        for (int j = 0; j < 4; j++) acc[i][j] = 0.f;

    for (int k0 = 0; k0 < K; k0 += 16) {
        __syncthreads();
#pragma unroll
        for (int i = 0; i < 4; i++) {
            int q = tid + i * 256;
            int mm = q >> 4, kk = q & 15;
            int gm = m0 + mm;
            As[kk][mm] = (gm < M) ? A[(size_t)gm * K + k0 + kk] : 0.f;
            int gn = n0 + mm;
            Ws[kk][mm] = W[(size_t)gn * K + k0 + kk];
        }
        __syncthreads();
#pragma unroll
        for (int kk = 0; kk < 16; kk++) {
            float a[4], w[4];
#pragma unroll
            for (int i = 0; i < 4; i++) a[i] = As[kk][tm * 4 + i];
#pragma unroll
            for (int j = 0; j < 4; j++) w[j] = Ws[kk][tn * 4 + j];
#pragma unroll
            for (int i = 0; i < 4; i++)
#pragma unroll
                for (int j = 0; j < 4; j++) acc[i][j] = fmaf(a[i], w[j], acc[i][j]);
        }
    }
#pragma unroll
    for (int i = 0; i < 4; i++) {
        int gm = m0 + tm * 4 + i;
        if (gm < M) {
#pragma unroll
            for (int j = 0; j < 4; j++) {
                int gn = n0 + tn * 4 + j;
                C[(size_t)gm * N + gn] = acc[i][j] + bias[gn];
            }
        }
    }
}

// =====================================================================
// K3: mma.sync bf16 joint GEMM + fused log-softmax stats
// =====================================================================
__device__ __forceinline__ void load_b_tile(int bt, uint32_t b_base, int tid) {
    uint32_t buf = b_base + (uint32_t)(bt % NBUF) * BT_BYTES;
    const int nc = bt >> 2, ktl = bt & 3;
    const int n = tid >> 1;
    const int c0 = (tid & 1) * 8;
    const __nv_bfloat16* src = g_wp + ((size_t)(nc * 128 + n) * DJ + ktl * 128 + c0 * 8);
    const uint32_t row = buf + (uint32_t)n * 256u;
    const uint32_t sw = (uint32_t)(n & 7);
#pragma unroll
    for (int j = 0; j < 8; j++) {
        uint32_t c = (uint32_t)(c0 + j);
        cp_async16(row + ((c ^ sw) << 4), src + j * 8);
    }
    asm volatile("cp.async.commit_group;" ::: "memory");
}

__global__ void __launch_bounds__(256, 1) joint_kernel(const int* __restrict__ targets)
{
    extern __shared__ __align__(16) char dyn[];
    __shared__ int tgtm[MTILE];

    const uint32_t base = (smem_u32(dyn) + 1023u) & ~1023u;
    const uint32_t a_base = base;
    const uint32_t b_base = base + A_BYTES;

    const int tid  = threadIdx.x;
    const int lane = tid & 31;
    const int wid  = tid >> 5;
    const int warp_m = wid & 3;     // 4 M-warps of 32 rows
    const int warp_n = wid >> 2;    // 2 N-warps of 64 cols
    const int g0 = blockIdx.x * MTILE;
    const unsigned FM = 0xffffffffu;

    if (tid < MTILE) {
        int g = g0 + tid;
        int b = g / (TT * UP);
        int r = g - b * (TT * UP);
        int u = r % UP;
        tgtm[tid] = (u < UU) ? targets[b * UU + u] : -1;
    }

    // ---- generate h tile into XOR-swizzled A (bf16) ----
    {
        const int m = tid >> 1;
        const int khalf = (tid & 1) * 256;
        int g = g0 + m;
        int b = g / (TT * UP);
        int r = g - b * (TT * UP);
        int t = r / UP, u = r - t * UP;
        const float4* er = reinterpret_cast<const float4*>(
            g_enc_h + ((size_t)(b * TT + t)) * DJ + khalf);
        const float4* dr = reinterpret_cast<const float4*>(
            g_dec_h + ((size_t)(b * UP + u)) * DJ + khalf);
        const uint32_t mrow = a_base + (uint32_t)m * 1024u;
        const uint32_t msw = (uint32_t)(m & 7);
#pragma unroll 4
        for (int i = 0; i < 32; i++) {
            int k = khalf + i * 8;
            float4 e0 = er[i * 2], e1 = er[i * 2 + 1];
            float4 d0 = dr[i * 2], d1 = dr[i * 2 + 1];
            uint32_t p0 = pack_bf16x2(tanh_fast(e0.x * d0.x), tanh_fast(e0.y * d0.y));
            uint32_t p1 = pack_bf16x2(tanh_fast(e0.z * d0.z), tanh_fast(e0.w * d0.w));
            uint32_t p2 = pack_bf16x2(tanh_fast(e1.x * d1.x), tanh_fast(e1.y * d1.y));
            uint32_t p3 = pack_bf16x2(tanh_fast(e1.z * d1.z), tanh_fast(e1.w * d1.w));
            uint32_t c = (uint32_t)(k >> 3);
            uint32_t addr = mrow + ((c ^ msw) << 4);
            asm volatile("st.shared.v4.b32 [%0], {%1,%2,%3,%4};"
                         :: "r"(addr), "r"(p0), "r"(p1), "r"(p2), "r"(p3) : "memory");
        }
    }
    __syncthreads();

    // ---- prologue: prefetch B tiles 0,1 ----
    load_b_tile(0, b_base, tid);
    load_b_tile(1, b_base, tid);

    // ---- per-lane ldmatrix addressing ----
    const int rowA = warp_m * 32 + (lane & 15);
    const uint32_t a_lane = a_base + (uint32_t)rowA * 1024u;
    const uint32_t swzA = (uint32_t)(rowA & 7);
    const uint32_t cbaseA = (uint32_t)(lane >> 4);
    const int n_row_base = warp_n * 64 + ((lane >> 4) << 3) + (lane & 7);
    const uint32_t kh = (uint32_t)((lane >> 3) & 1);
    const uint32_t swzB = (uint32_t)(lane & 7);
    uint32_t rowoffB[4];
#pragma unroll
    for (int p = 0; p < 4; p++) rowoffB[p] = (uint32_t)(n_row_base + p * 16) * 256u;

    // ---- per-row epilogue state (no max: logits provably bounded) ----
    float sm[4], blankv[4], tgtv[4];
    int tg[4];
#pragma unroll
    for (int g = 0; g < 4; g++) {
        sm[g] = 0.f; blankv[g] = 0.f; tgtv[g] = 0.f;
        int m = warp_m * 32 + (g >> 1) * 16 + (g & 1) * 8 + (lane >> 2);
        tg[g] = tgtm[m];
    }

    float acc[2][8][4];

#pragma unroll 1
    for (int bt = 0; bt < NTILES; bt++) {
        const int ktl = bt & 3;
        if (bt < NTILES - 1) asm volatile("cp.async.wait_group 1;" ::: "memory");
        else                 asm volatile("cp.async.wait_group 0;" ::: "memory");
        __syncthreads();
        if (bt + 2 < NTILES) load_b_tile(bt + 2, b_base, tid);

        if (ktl == 0) {
#pragma unroll
            for (int mi = 0; mi < 2; mi++)
#pragma unroll
                for (int nf = 0; nf < 8; nf++)
#pragma unroll
                    for (int j = 0; j < 4; j++) acc[mi][nf][j] = 0.f;
        }

        const uint32_t bbuf = b_base + (uint32_t)(bt % NBUF) * BT_BYTES;
#pragma unroll
        for (int s = 0; s < 8; s++) {
            uint32_t a0[4], a1[4];
            uint32_t cA = (uint32_t)((ktl * 8 + s) * 2) + cbaseA;
            uint32_t aaddr = a_lane + ((cA ^ swzA) << 4);
            ldsm_x4(a0, aaddr);
            ldsm_x4(a1, aaddr + 16384u);
            uint32_t b[4][4];
            uint32_t cB = ((uint32_t)(s * 2) + kh) ^ swzB;
#pragma unroll
            for (int p = 0; p < 4; p++)
                ldsm_x4(b[p], bbuf + rowoffB[p] + (cB << 4));
#pragma unroll
            for (int p = 0; p < 4; p++) {
                mma_bf16(acc[0][2 * p],     a0, b[p][0], b[p][1]);
                mma_bf16(acc[0][2 * p + 1], a0, b[p][2], b[p][3]);
                mma_bf16(acc[1][2 * p],     a1, b[p][0], b[p][1]);
                mma_bf16(acc[1][2 * p + 1], a1, b[p][2], b[p][3]);
            }
        }

        if (ktl == 3) {
            const int nc = bt >> 2;
            const int vbase = nc * 128 + warp_n * 64 + (lane & 3) * 2;
#pragma unroll
            for (int g = 0; g < 4; g++) {
                const int mi = g >> 1, hf = (g & 1) * 2;
                float ls = 0.f;
#pragma unroll
                for (int nf = 0; nf < 8; nf++)
                    ls += __expf(acc[mi][nf][hf]) + __expf(acc[mi][nf][hf + 1]);
                ls += __shfl_xor_sync(FM, ls, 1);
                ls += __shfl_xor_sync(FM, ls, 2);
                sm[g] += ls;
#pragma unroll
                for (int nf = 0; nf < 8; nf++) {
                    int v0 = vbase + nf * 8;
                    if (v0 == 0)         blankv[g] = acc[mi][nf][hf];
                    if (v0 == tg[g])     tgtv[g]   = acc[mi][nf][hf];
                    if (v0 + 1 == tg[g]) tgtv[g]   = acc[mi][nf][hf + 1];
                }
            }
        }
    }

    // gather captured values across the 4 lanes of each row group
#pragma unroll
    for (int g = 0; g < 4; g++) {
        tgtv[g]   += __shfl_xor_sync(FM, tgtv[g], 1);
        tgtv[g]   += __shfl_xor_sync(FM, tgtv[g], 2);
        blankv[g] += __shfl_xor_sync(FM, blankv[g], 1);
        blankv[g] += __shfl_xor_sync(FM, blankv[g], 2);
    }

    // reuse B buffer smem for the cross-half combine (B no longer needed)
    __syncthreads();
    float* ssum   = reinterpret_cast<float*>(dyn) + ((b_base - smem_u32(dyn)) >> 2);
    float* stgtv  = ssum + 2 * MTILE;
    float* sblank = stgtv + 2 * MTILE;

    if ((lane & 3) == 0) {
#pragma unroll
        for (int g = 0; g < 4; g++) {
            int m = warp_m * 32 + (g >> 1) * 16 + (g & 1) * 8 + (lane >> 2);
            ssum[warp_n * MTILE + m]  = sm[g];
            stgtv[warp_n * MTILE + m] = tgtv[g];
            if (warp_n == 0) sblank[m] = blankv[g];
        }
    }
    __syncthreads();

    if (tid < MTILE) {
        int m = tid;
        float lse = __logf(ssum[m] + ssum[MTILE + m]);
        int g = g0 + m;
        int b = g / (TT * UP);
        int r = g - b * (TT * UP);
        int t = r / UP, u = r - t * UP;
        g_blank[g] = sblank[m] - lse;
        if (u < UU) {
            int h = (tgtm[m] >> 6) & 1;
            g_emit[(size_t)(b * TT + t) * UU + u] = stgtv[h * MTILE + m] - lse;
        }
    }
}

// =====================================================================
// K4: alpha DP — fused (E,M,S) semiring scan, one warp per batch
// =====================================================================
__global__ void dp_kernel(const int* __restrict__ in_len, const int* __restrict__ tgt_len) {
    const int b = blockIdx.x;
    const int lane = threadIdx.x;
    const float* blank = g_blank + (size_t)b * TT * UP;
    const float* emit  = g_emit  + (size_t)b * TT * UU;
    const int til = in_len[b];
    const int ul  = tgt_len[b];
    const int u0 = lane * 3;
    const unsigned FM = 0xffffffffu;
    const bool a0ok = (u0 < UP), a1ok = (u0 + 1 < UP), a2ok = (u0 + 2 < UP);

    float alpha[3];

    // --- t = 0: alpha0 = inclusive cumsum
    {
        float x0 = (u0 >= 1 && a0ok) ? emit[u0 - 1] : 0.f;
        float x1 = a1ok ? emit[u0] : 0.f;
        float x2 = a2ok ? emit[u0 + 1] : 0.f;
        float s0 = x0, s1 = s0 + x1, s2 = s1 + x2;
        float tot = s2;
#pragma unroll
        for (int o = 1; o < 32; o <<= 1) {
            float n = __shfl_up_sync(FM, tot, o);
            if (lane >= o) tot += n;
        }
        float ex = __shfl_up_sync(FM, tot, 1);
        if (lane == 0) ex = 0.f;
        alpha[0] = ex + s0; alpha[1] = ex + s1; alpha[2] = ex + s2;
    }

    float bl[3], xe[3];
    {
        const float* bp = blank;
        bl[0] = a0ok ? bp[u0] : 0.f;
        bl[1] = a1ok ? bp[u0 + 1] : 0.f;
        bl[2] = a2ok ? bp[u0 + 2] : 0.f;
        const float* ep = emit + UU;
        xe[0] = (u0 >= 1 && a0ok) ? ep[u0 - 1] : 0.f;
        xe[1] = a1ok ? ep[u0] : 0.f;
        xe[2] = a2ok ? ep[u0 + 1] : 0.f;
    }

    for (int t = 1; t < til; t++) {
        float nbl[3], nxe[3];
        if (t + 1 < til) {
            const float* bp = blank + (size_t)t * UP;
            nbl[0] = a0ok ? bp[u0] : 0.f;
            nbl[1] = a1ok ? bp[u0 + 1] : 0.f;
            nbl[2] = a2ok ? bp[u0 + 2] : 0.f;
            const float* ep = emit + (size_t)(t + 1) * UU;
            nxe[0] = (u0 >= 1 && a0ok) ? ep[u0 - 1] : 0.f;
            nxe[1] = a1ok ? ep[u0] : 0.f;
            nxe[2] = a2ok ? ep[u0 + 1] : 0.f;
        }

        // element u: eps = emit[t][u-1] (0 for u=0), tmp = alpha + blank_prev
        float tmp0 = a0ok ? (alpha[0] + bl[0]) : -1e30f;
        float tmp1 = a1ok ? (alpha[1] + bl[1]) : -1e30f;
        float tmp2 = a2ok ? (alpha[2] + bl[2]) : -1e30f;

        // intra-lane inclusive prefixes of (E,M,S)
        float E0 = xe[0], M0 = tmp0, S0 = 1.f;
        float t1 = M0 + xe[1];
        float M1 = fmaxf(t1, tmp1);
        float S1 = S0 * __expf(t1 - M1) + __expf(tmp1 - M1);
        float E1 = E0 + xe[1];
        float t2 = M1 + xe[2];
        float M2 = fmaxf(t2, tmp2);
        float S2 = S1 * __expf(t2 - M2) + __expf(tmp2 - M2);
        float E2 = E1 + xe[2];

        // warp inclusive scan on lane aggregates
        float Ew = E2, Mw = M2, Sw = S2;
#pragma unroll
        for (int o = 1; o < 32; o <<= 1) {
            float Ep = __shfl_up_sync(FM, Ew, o);
            float Mp = __shfl_up_sync(FM, Mw, o);
            float Sp = __shfl_up_sync(FM, Sw, o);
            if (lane >= o) {
                float tt = Mp + Ew;
                float nm = fmaxf(tt, Mw);
                Sw = Sp * __expf(tt - nm) + Sw * __expf(Mw - nm);
                Mw = nm;
                Ew = Ep + Ew;
            }
        }
        // exclusive prefix
        float Pe = __shfl_up_sync(FM, Ew, 1);
        float Pm = __shfl_up_sync(FM, Mw, 1);
        float Ps = __shfl_up_sync(FM, Sw, 1);
        if (lane == 0) { Pe = 0.f; Pm = -1e30f; Ps = 0.f; }

        // alpha[i] = (P ∘ intra_i).M + log(S)
        {
            float tt = Pm + E0;
            float nm = fmaxf(tt, M0);
            float S = Ps * __expf(tt - nm) + S0 * __expf(M0 - nm);
            alpha[0] = nm + __logf(S);
        }
        {
            float tt = Pm + E1;
            float nm = fmaxf(tt, M1);
            float S = Ps * __expf(tt - nm) + S1 * __expf(M1 - nm);
            alpha[1] = nm + __logf(S);
        }
        {
            float tt = Pm + E2;
            float nm = fmaxf(tt, M2);
            float S = Ps * __expf(tt - nm) + S2 * __expf(M2 - nm);
            alpha[2] = nm + __logf(S);
        }

        bl[0] = nbl[0]; bl[1] = nbl[1]; bl[2] = nbl[2];
        xe[0] = nxe[0]; xe[1] = nxe[1]; xe[2] = nxe[2];
    }

    int j = ul - u0;
    if (j >= 0 && j < 3) {
        float a = (j == 0) ? alpha[0] : (j == 1) ? alpha[1] : alpha[2];
        g_final[b] = a + blank[(size_t)(til - 1) * UP + ul];
    }
}

__global__ void finalize_kernel(float* out) {
    out[0] = -0.25f * (g_final[0] + g_final[1] + g_final[2] + g_final[3]);
}

// =====================================================================
// launch
// =====================================================================
extern "C" void kernel_launch(void* const* d_in, const int* in_sizes, int n_in,
                              void* d_out, int out_size)
{
    const float* enc     = (const float*)d_in[0];
    const float* dec     = (const float*)d_in[1];
    const int*   targets = (const int*)  d_in[2];
    const int*   in_len  = (const int*)  d_in[3];
    const int*   tgt_len = (const int*)  d_in[4];
    const float* W_enc   = (const float*)d_in[5];
    const float* b_enc   = (const float*)d_in[6];
    const float* W_dec   = (const float*)d_in[7];
    const float* b_dec   = (const float*)d_in[8];
    const float* W_proj  = (const float*)d_in[9];

    void *pe = nullptr, *pd = nullptr;
    cudaGetSymbolAddress(&pe, g_enc_h);
    cudaGetSymbolAddress(&pd, g_dec_h);

    const int smem_joint = 1024 + A_BYTES + NBUF * BT_BYTES;   // 230400 B
    cudaFuncSetAttribute(joint_kernel, cudaFuncAttributeMaxDynamicSharedMemorySize, smem_joint);

    convert_wp_kernel<<<(VV * DJ) / 256, 256>>>(W_proj);

    dim3 g1((BB * TT + 63) / 64, DJ / 64);
    gemm_bias_kernel<<<g1, 256>>>(enc, W_enc, b_enc, (float*)pe, BB * TT, DJ, 512);

    dim3 g2((BB * UP + 63) / 64, DJ / 64);
    gemm_bias_kernel<<<g2, 256>>>(dec, W_dec, b_dec, (float*)pd, BB * UP, DJ, 512);

    joint_kernel<<<(BB * TT * UP) / MTILE, 256, smem_joint>>>(targets);

    dp_kernel<<<BB, 32>>>(in_len, tgt_len);

    finalize_kernel<<<1, 1>>>((float*)d_out);
}

// round 5
// speedup vs baseline: 3.8223x; 1.0956x over previous
#include <cuda_runtime.h>
#include <cuda_bf16.h>
#include <math.h>
#include <stdint.h>

#define BB 4
#define TT 256
#define UU 64
#define UP 65          // U+1
#define DJ 512
#define VV 1024
#define MTILE 128      // lattice rows per joint CTA
#define A_BYTES (MTILE*DJ*2)     // 131072
#define BT_BYTES (128*256)       // 32768: 128n x 128k bf16, XOR-swizzled 256B rows
#define NBUF 3
#define NTILES 32                // 8 nc x 4 ktile
#define JTHREADS 512

// ---------------- scratch ----------------
__device__ float g_enc_h[BB*TT*DJ];
__device__ float g_dec_h[BB*UP*DJ];
__device__ float g_blank[BB*TT*UP];
__device__ float g_emit [BB*TT*UU];
__device__ float g_final[BB];
__device__ __nv_bfloat16 g_wp[VV*DJ];   // W_proj bf16 [V][K] row-major

// ---------------- helpers ----------------
__device__ __forceinline__ uint32_t smem_u32(const void* p) {
    uint32_t a;
    asm("{ .reg .u64 t; cvta.to.shared.u64 t, %1; cvt.u32.u64 %0, t; }" : "=r"(a) : "l"(p));
    return a;
}
__device__ __forceinline__ float tanh_fast(float x) {
    float r; asm("tanh.approx.f32 %0, %1;" : "=f"(r) : "f"(x)); return r;
}
__device__ __forceinline__ uint32_t pack_bf16x2(float lo, float hi) {
    uint32_t r; asm("cvt.rn.bf16x2.f32 %0, %1, %2;" : "=r"(r) : "f"(hi), "f"(lo)); return r;
}
__device__ __forceinline__ void cp_async16(uint32_t dst, const void* src) {
    asm volatile("cp.async.cg.shared.global [%0], [%1], 16;\n" :: "r"(dst), "l"(src) : "memory");
}
__device__ __forceinline__ void ldsm_x4(uint32_t (&r)[4], uint32_t addr) {
    asm volatile("ldmatrix.sync.aligned.m8n8.x4.shared.b16 {%0,%1,%2,%3}, [%4];"
                 : "=r"(r[0]), "=r"(r[1]), "=r"(r[2]), "=r"(r[3]) : "r"(addr));
}
__device__ __forceinline__ void mma_bf16(float (&c)[4], const uint32_t (&a)[4],
                                         uint32_t b0, uint32_t b1) {
    asm volatile(
        "mma.sync.aligned.m16n8k16.row.col.f32.bf16.bf16.f32 "
        "{%0,%1,%2,%3}, {%4,%5,%6,%7}, {%8,%9}, {%0,%1,%2,%3};"
        : "+f"(c[0]), "+f"(c[1]), "+f"(c[2]), "+f"(c[3])
        : "r"(a[0]), "r"(a[1]), "r"(a[2]), "r"(a[3]), "r"(b0), "r"(b1));
}

// =====================================================================
// K0: W_proj fp32 -> bf16
// =====================================================================
__global__ void convert_wp_kernel(const float* __restrict__ Wp) {
    int idx = blockIdx.x * 256 + threadIdx.x;
    g_wp[idx] = __float2bfloat16(Wp[idx]);
}

// =====================================================================
// K1/K2: C[M,N] = A[M,K] @ W[N,K]^T + bias[N]
// =====================================================================
__global__ void __launch_bounds__(256) gemm_bias_kernel(
    const float* __restrict__ A, const float* __restrict__ W,
    const float* __restrict__ bias, float* __restrict__ C,
    int M, int N, int K)
{
    __shared__ float As[16][64];
    __shared__ float Ws[16][64];
    const int m0 = blockIdx.x * 64;
    const int n0 = blockIdx.y * 64;
    const int tid = threadIdx.x;
    const int tm = tid >> 4, tn = tid & 15;

    float acc[4][4];
#pragma unroll
    for (int i = 0; i < 4; i++)
#pragma unroll
        for (int j = 0; j < 4; j++) acc[i][j] = 0.f;

    for (int k0 = 0; k0 < K; k0 += 16) {
        __syncthreads();
#pragma unroll
        for (int i = 0; i < 4; i++) {
            int q = tid + i * 256;
            int mm = q >> 4, kk = q & 15;
            int gm = m0 + mm;
            As[kk][mm] = (gm < M) ? A[(size_t)gm * K + k0 + kk] : 0.f;
            int gn = n0 + mm;
            Ws[kk][mm] = W[(size_t)gn * K + k0 + kk];
        }
        __syncthreads();
#pragma unroll
        for (int kk = 0; kk < 16; kk++) {
            float a[4], w[4];
#pragma unroll
            for (int i = 0; i < 4; i++) a[i] = As[kk][tm * 4 + i];
#pragma unroll
            for (int j = 0; j < 4; j++) w[j] = Ws[kk][tn * 4 + j];
#pragma unroll
            for (int i = 0; i < 4; i++)
#pragma unroll
                for (int j = 0; j < 4; j++) acc[i][j] = fmaf(a[i], w[j], acc[i][j]);
        }
    }
#pragma unroll
    for (int i = 0; i < 4; i++) {
        int gm = m0 + tm * 4 + i;
        if (gm < M) {
#pragma unroll
            for (int j = 0; j < 4; j++) {
                int gn = n0 + tn * 4 + j;
                C[(size_t)gm * N + gn] = acc[i][j] + bias[gn];
            }
        }
    }
}

// =====================================================================
// K3: mma.sync bf16 joint GEMM + fused log-softmax stats  (512 thr)
// =====================================================================
__device__ __forceinline__ void load_b_tile(int bt, uint32_t b_base, int tid) {
    uint32_t buf = b_base + (uint32_t)(bt % NBUF) * BT_BYTES;
    const int nc = bt >> 2, ktl = bt & 3;
    const int n = tid >> 2;
    const int c0 = (tid & 3) * 4;
    const __nv_bfloat16* src = g_wp + ((size_t)(nc * 128 + n) * DJ + ktl * 128 + c0 * 8);
    const uint32_t row = buf + (uint32_t)n * 256u;
    const uint32_t sw = (uint32_t)(n & 7);
#pragma unroll
    for (int j = 0; j < 4; j++) {
        uint32_t c = (uint32_t)(c0 + j);
        cp_async16(row + ((c ^ sw) << 4), src + j * 8);
    }
    asm volatile("cp.async.commit_group;" ::: "memory");
}

__global__ void __launch_bounds__(JTHREADS, 1) joint_kernel(const int* __restrict__ targets)
{
    extern __shared__ __align__(16) char dyn[];
    __shared__ int tgtm[MTILE];

    const uint32_t base = (smem_u32(dyn) + 1023u) & ~1023u;
    const uint32_t a_base = base;
    const uint32_t b_base = base + A_BYTES;

    const int tid  = threadIdx.x;
    const int lane = tid & 31;
    const int wid  = tid >> 5;
    const int warp_m = wid & 3;     // 4 M-warps of 32 rows
    const int warp_n = wid >> 2;    // 4 N-warps of 32 cols
    const int g0 = blockIdx.x * MTILE;
    const unsigned FM = 0xffffffffu;

    if (tid < MTILE) {
        int g = g0 + tid;
        int b = g / (TT * UP);
        int r = g - b * (TT * UP);
        int u = r % UP;
        tgtm[tid] = (u < UU) ? targets[b * UU + u] : -1;
    }

    // ---- generate h tile into XOR-swizzled A (bf16); each thread 128 k ----
    {
        const int m = tid >> 2;
        const int kq = (tid & 3) * 128;
        int g = g0 + m;
        int b = g / (TT * UP);
        int r = g - b * (TT * UP);
        int t = r / UP, u = r - t * UP;
        const float4* er = reinterpret_cast<const float4*>(
            g_enc_h + ((size_t)(b * TT + t)) * DJ + kq);
        const float4* dr = reinterpret_cast<const float4*>(
            g_dec_h + ((size_t)(b * UP + u)) * DJ + kq);
        const uint32_t mrow = a_base + (uint32_t)m * 1024u;
        const uint32_t msw = (uint32_t)(m & 7);
#pragma unroll 4
        for (int i = 0; i < 16; i++) {
            int k = kq + i * 8;
            float4 e0 = er[i * 2], e1 = er[i * 2 + 1];
            float4 d0 = dr[i * 2], d1 = dr[i * 2 + 1];
            uint32_t p0 = pack_bf16x2(tanh_fast(e0.x * d0.x), tanh_fast(e0.y * d0.y));
            uint32_t p1 = pack_bf16x2(tanh_fast(e0.z * d0.z), tanh_fast(e0.w * d0.w));
            uint32_t p2 = pack_bf16x2(tanh_fast(e1.x * d1.x), tanh_fast(e1.y * d1.y));
            uint32_t p3 = pack_bf16x2(tanh_fast(e1.z * d1.z), tanh_fast(e1.w * d1.w));
            uint32_t c = (uint32_t)(k >> 3);
            uint32_t addr = mrow + ((c ^ msw) << 4);
            asm volatile("st.shared.v4.b32 [%0], {%1,%2,%3,%4};"
                         :: "r"(addr), "r"(p0), "r"(p1), "r"(p2), "r"(p3) : "memory");
        }
    }
    __syncthreads();

    // ---- prologue: prefetch B tiles 0,1 ----
    load_b_tile(0, b_base, tid);
    load_b_tile(1, b_base, tid);

    // ---- per-lane ldmatrix addressing ----
    const int rowA = warp_m * 32 + (lane & 15);
    const uint32_t a_lane = a_base + (uint32_t)rowA * 1024u;
    const uint32_t swzA = (uint32_t)(rowA & 7);
    const uint32_t cbaseA = (uint32_t)(lane >> 4);
    const int n_row_base = warp_n * 32 + ((lane >> 4) << 3) + (lane & 7);
    const uint32_t kh = (uint32_t)((lane >> 3) & 1);
    const uint32_t swzB = (uint32_t)(lane & 7);
    uint32_t rowoffB[2];
#pragma unroll
    for (int p = 0; p < 2; p++) rowoffB[p] = (uint32_t)(n_row_base + p * 16) * 256u;

    // ---- per-row epilogue state ----
    float sm[4], blankv[4], tgtv[4];
    int tg[4];
#pragma unroll
    for (int g = 0; g < 4; g++) {
        sm[g] = 0.f; blankv[g] = 0.f; tgtv[g] = 0.f;
        int m = warp_m * 32 + (g >> 1) * 16 + (g & 1) * 8 + (lane >> 2);
        tg[g] = tgtm[m];
    }

    float acc[2][4][4];

#pragma unroll 1
    for (int bt = 0; bt < NTILES; bt++) {
        const int ktl = bt & 3;
        if (bt < NTILES - 1) asm volatile("cp.async.wait_group 1;" ::: "memory");
        else                 asm volatile("cp.async.wait_group 0;" ::: "memory");
        __syncthreads();
        if (bt + 2 < NTILES) load_b_tile(bt + 2, b_base, tid);

        if (ktl == 0) {
#pragma unroll
            for (int mi = 0; mi < 2; mi++)
#pragma unroll
                for (int nf = 0; nf < 4; nf++)
#pragma unroll
                    for (int j = 0; j < 4; j++) acc[mi][nf][j] = 0.f;
        }

        const uint32_t bbuf = b_base + (uint32_t)(bt % NBUF) * BT_BYTES;
#pragma unroll
        for (int s = 0; s < 8; s++) {
            uint32_t a0[4], a1[4];
            uint32_t cA = (uint32_t)((ktl * 8 + s) * 2) + cbaseA;
            uint32_t aaddr = a_lane + ((cA ^ swzA) << 4);
            ldsm_x4(a0, aaddr);
            ldsm_x4(a1, aaddr + 16384u);
            uint32_t b[2][4];
            uint32_t cB = ((uint32_t)(s * 2) + kh) ^ swzB;
#pragma unroll
            for (int p = 0; p < 2; p++)
                ldsm_x4(b[p], bbuf + rowoffB[p] + (cB << 4));
#pragma unroll
            for (int p = 0; p < 2; p++) {
                mma_bf16(acc[0][2 * p],     a0, b[p][0], b[p][1]);
                mma_bf16(acc[0][2 * p + 1], a0, b[p][2], b[p][3]);
                mma_bf16(acc[1][2 * p],     a1, b[p][0], b[p][1]);
                mma_bf16(acc[1][2 * p + 1], a1, b[p][2], b[p][3]);
            }
        }

        if (ktl == 3) {
            const int nc = bt >> 2;
            const int vbase = nc * 128 + warp_n * 32 + (lane & 3) * 2;
#pragma unroll
            for (int g = 0; g < 4; g++) {
                const int mi = g >> 1, hf = (g & 1) * 2;
                float ls = 0.f;
#pragma unroll
                for (int nf = 0; nf < 4; nf++)
                    ls += __expf(acc[mi][nf][hf]) + __expf(acc[mi][nf][hf + 1]);
                ls += __shfl_xor_sync(FM, ls, 1);
                ls += __shfl_xor_sync(FM, ls, 2);
                sm[g] += ls;
#pragma unroll
                for (int nf = 0; nf < 4; nf++) {
                    int v0 = vbase + nf * 8;
                    if (v0 == 0)         blankv[g] = acc[mi][nf][hf];
                    if (v0 == tg[g])     tgtv[g]   = acc[mi][nf][hf];
                    if (v0 + 1 == tg[g]) tgtv[g]   = acc[mi][nf][hf + 1];
                }
            }
        }
    }

    // gather captured values across the 4 lanes of each row group
#pragma unroll
    for (int g = 0; g < 4; g++) {
        tgtv[g]   += __shfl_xor_sync(FM, tgtv[g], 1);
        tgtv[g]   += __shfl_xor_sync(FM, tgtv[g], 2);
        blankv[g] += __shfl_xor_sync(FM, blankv[g], 1);
        blankv[g] += __shfl_xor_sync(FM, blankv[g], 2);
    }

    // reuse B buffer smem for the cross-n-warp combine
    __syncthreads();
    float* ssum   = reinterpret_cast<float*>(dyn) + ((b_base - smem_u32(dyn)) >> 2);
    float* stgtv  = ssum + 4 * MTILE;
    float* sblank = stgtv + 4 * MTILE;

    if ((lane & 3) == 0) {
#pragma unroll
        for (int g = 0; g < 4; g++) {
            int m = warp_m * 32 + (g >> 1) * 16 + (g & 1) * 8 + (lane >> 2);
            ssum[warp_n * MTILE + m]  = sm[g];
            stgtv[warp_n * MTILE + m] = tgtv[g];
            if (warp_n == 0) sblank[m] = blankv[g];
        }
    }
    __syncthreads();

    if (tid < MTILE) {
        int m = tid;
        float lse = __logf(ssum[m] + ssum[MTILE + m] + ssum[2 * MTILE + m] + ssum[3 * MTILE + m]);
        int g = g0 + m;
        int b = g / (TT * UP);
        int r = g - b * (TT * UP);
        int t = r / UP, u = r - t * UP;
        g_blank[g] = sblank[m] - lse;
        if (u < UU) {
            int h = (tgtm[m] >> 5) & 3;
            g_emit[(size_t)(b * TT + t) * UU + u] = stgtv[h * MTILE + m] - lse;
        }
    }
}

// =====================================================================
// K4: alpha DP — fused (E,M,S) semiring scan, one warp per batch
// =====================================================================
__global__ void dp_kernel(const int* __restrict__ in_len, const int* __restrict__ tgt_len) {
    const int b = blockIdx.x;
    const int lane = threadIdx.x;
    const float* blank = g_blank + (size_t)b * TT * UP;
    const float* emit  = g_emit  + (size_t)b * TT * UU;
    const int til = in_len[b];
    const int ul  = tgt_len[b];
    const int u0 = lane * 3;
    const unsigned FM = 0xffffffffu;
    const bool a0ok = (u0 < UP), a1ok = (u0 + 1 < UP), a2ok = (u0 + 2 < UP);

    float alpha[3];

    {
        float x0 = (u0 >= 1 && a0ok) ? emit[u0 - 1] : 0.f;
        float x1 = a1ok ? emit[u0] : 0.f;
        float x2 = a2ok ? emit[u0 + 1] : 0.f;
        float s0 = x0, s1 = s0 + x1, s2 = s1 + x2;
        float tot = s2;
#pragma unroll
        for (int o = 1; o < 32; o <<= 1) {
            float n = __shfl_up_sync(FM, tot, o);
            if (lane >= o) tot += n;
        }
        float ex = __shfl_up_sync(FM, tot, 1);
        if (lane == 0) ex = 0.f;
        alpha[0] = ex + s0; alpha[1] = ex + s1; alpha[2] = ex + s2;
    }

    float bl[3], xe[3];
    {
        const float* bp = blank;
        bl[0] = a0ok ? bp[u0] : 0.f;
        bl[1] = a1ok ? bp[u0 + 1] : 0.f;
        bl[2] = a2ok ? bp[u0 + 2] : 0.f;
        const float* ep = emit + UU;
        xe[0] = (u0 >= 1 && a0ok) ? ep[u0 - 1] : 0.f;
        xe[1] = a1ok ? ep[u0] : 0.f;
        xe[2] = a2ok ? ep[u0 + 1] : 0.f;
    }

    for (int t = 1; t < til; t++) {
        float nbl[3], nxe[3];
        if (t + 1 < til) {
            const float* bp = blank + (size_t)t * UP;
            nbl[0] = a0ok ? bp[u0] : 0.f;
            nbl[1] = a1ok ? bp[u0 + 1] : 0.f;
            nbl[2] = a2ok ? bp[u0 + 2] : 0.f;
            const float* ep = emit + (size_t)(t + 1) * UU;
            nxe[0] = (u0 >= 1 && a0ok) ? ep[u0 - 1] : 0.f;
            nxe[1] = a1ok ? ep[u0] : 0.f;
            nxe[2] = a2ok ? ep[u0 + 1] : 0.f;
        }

        float tmp0 = a0ok ? (alpha[0] + bl[0]) : -1e30f;
        float tmp1 = a1ok ? (alpha[1] + bl[1]) : -1e30f;
        float tmp2 = a2ok ? (alpha[2] + bl[2]) : -1e30f;

        float E0 = xe[0], M0 = tmp0, S0 = 1.f;
        float t1 = M0 + xe[1];
        float M1 = fmaxf(t1, tmp1);
        float S1 = S0 * __expf(t1 - M1) + __expf(tmp1 - M1);
        float E1 = E0 + xe[1];
        float t2 = M1 + xe[2];
        float M2 = fmaxf(t2, tmp2);
        float S2 = S1 * __expf(t2 - M2) + __expf(tmp2 - M2);
        float E2 = E1 + xe[2];

        float Ew = E2, Mw = M2, Sw = S2;
#pragma unroll
        for (int o = 1; o < 32; o <<= 1) {
            float Ep = __shfl_up_sync(FM, Ew, o);
            float Mp = __shfl_up_sync(FM, Mw, o);
            float Sp = __shfl_up_sync(FM, Sw, o);
            if (lane >= o) {
                float tt = Mp + Ew;
                float nm = fmaxf(tt, Mw);
                Sw = Sp * __expf(tt - nm) + Sw * __expf(Mw - nm);
                Mw = nm;
                Ew = Ep + Ew;
            }
        }
        float Pe = __shfl_up_sync(FM, Ew, 1);
        float Pm = __shfl_up_sync(FM, Mw, 1);
        float Ps = __shfl_up_sync(FM, Sw, 1);
        if (lane == 0) { Pe = 0.f; Pm = -1e30f; Ps = 0.f; }

        {
            float tt = Pm + E0;
            float nm = fmaxf(tt, M0);
            float S = Ps * __expf(tt - nm) + S0 * __expf(M0 - nm);
            alpha[0] = nm + __logf(S);
        }
        {
            float tt = Pm + E1;
            float nm = fmaxf(tt, M1);
            float S = Ps * __expf(tt - nm) + S1 * __expf(M1 - nm);
            alpha[1] = nm + __logf(S);
        }
        {
            float tt = Pm + E2;
            float nm = fmaxf(tt, M2);
            float S = Ps * __expf(tt - nm) + S2 * __expf(M2 - nm);
            alpha[2] = nm + __logf(S);
        }

        bl[0] = nbl[0]; bl[1] = nbl[1]; bl[2] = nbl[2];
        xe[0] = nxe[0]; xe[1] = nxe[1]; xe[2] = nxe[2];
    }

    int j = ul - u0;
    if (j >= 0 && j < 3) {
        float a = (j == 0) ? alpha[0] : (j == 1) ? alpha[1] : alpha[2];
        g_final[b] = a + blank[(size_t)(til - 1) * UP + ul];
    }
}

__global__ void finalize_kernel(float* out) {
    out[0] = -0.25f * (g_final[0] + g_final[1] + g_final[2] + g_final[3]);
}

// =====================================================================
// launch
// =====================================================================
extern "C" void kernel_launch(void* const* d_in, const int* in_sizes, int n_in,
                              void* d_out, int out_size)
{
    const float* enc     = (const float*)d_in[0];
    const float* dec     = (const float*)d_in[1];
    const int*   targets = (const int*)  d_in[2];
    const int*   in_len  = (const int*)  d_in[3];
    const int*   tgt_len = (const int*)  d_in[4];
    const float* W_enc   = (const float*)d_in[5];
    const float* b_enc   = (const float*)d_in[6];
    const float* W_dec   = (const float*)d_in[7];
    const float* b_dec   = (const float*)d_in[8];
    const float* W_proj  = (const float*)d_in[9];

    void *pe = nullptr, *pd = nullptr;
    cudaGetSymbolAddress(&pe, g_enc_h);
    cudaGetSymbolAddress(&pd, g_dec_h);

    const int smem_joint = 1024 + A_BYTES + NBUF * BT_BYTES;   // 230400 B
    cudaFuncSetAttribute(joint_kernel, cudaFuncAttributeMaxDynamicSharedMemorySize, smem_joint);

    convert_wp_kernel<<<(VV * DJ) / 256, 256>>>(W_proj);

    dim3 g1((BB * TT + 63) / 64, DJ / 64);
    gemm_bias_kernel<<<g1, 256>>>(enc, W_enc, b_enc, (float*)pe, BB * TT, DJ, 512);

    dim3 g2((BB * UP + 63) / 64, DJ / 64);
    gemm_bias_kernel<<<g2, 256>>>(dec, W_dec, b_dec, (float*)pd, BB * UP, DJ, 512);

    joint_kernel<<<(BB * TT * UP) / MTILE, JTHREADS, smem_joint>>>(targets);

    dp_kernel<<<BB, 32>>>(in_len, tgt_len);

    finalize_kernel<<<1, 1>>>((float*)d_out);
}

// round 6
// speedup vs baseline: 3.8827x; 1.0158x over previous
#include <cuda_runtime.h>
#include <cuda_bf16.h>
#include <math.h>
#include <stdint.h>

#define BB 4
#define TT 256
#define UU 64
#define UP 65          // U+1
#define DJ 512
#define VV 1024
#define MTILE 128      // lattice rows per joint CTA
#define A_BYTES (MTILE*DJ*2)     // 131072
#define BT_BYTES (256*128)       // 32768: 256n x 64k bf16, 128B rows (SW128 atom)
#define NBUF 3
#define NTILES 32                // 4 nc x 8 ktile
#define JTHREADS 512

// ---------------- scratch ----------------
__device__ float g_enc_h[BB*TT*DJ];
__device__ float g_dec_h[BB*UP*DJ];
__device__ float g_blank[BB*TT*UP];
__device__ float g_emit [BB*TT*UU];
__device__ float g_final[BB];
__device__ __nv_bfloat16 g_wp[VV*DJ];   // W_proj bf16 [V][K] row-major

// ---------------- helpers ----------------
__device__ __forceinline__ uint32_t smem_u32(const void* p) {
    uint32_t a;
    asm("{ .reg .u64 t; cvta.to.shared.u64 t, %1; cvt.u32.u64 %0, t; }" : "=r"(a) : "l"(p));
    return a;
}
__device__ __forceinline__ float tanh_fast(float x) {
    float r; asm("tanh.approx.f32 %0, %1;" : "=f"(r) : "f"(x)); return r;
}
__device__ __forceinline__ uint32_t pack_bf16x2(float lo, float hi) {
    uint32_t r; asm("cvt.rn.bf16x2.f32 %0, %1, %2;" : "=r"(r) : "f"(hi), "f"(lo)); return r;
}
__device__ __forceinline__ void cp_async16(uint32_t dst, const void* src) {
    asm volatile("cp.async.cg.shared.global [%0], [%1], 16;\n" :: "r"(dst), "l"(src) : "memory");
}
__device__ __forceinline__ void ldsm_x4(uint32_t (&r)[4], uint32_t addr) {
    asm volatile("ldmatrix.sync.aligned.m8n8.x4.shared.b16 {%0,%1,%2,%3}, [%4];"
                 : "=r"(r[0]), "=r"(r[1]), "=r"(r[2]), "=r"(r[3]) : "r"(addr));
}
__device__ __forceinline__ void mma_bf16(float (&c)[4], const uint32_t (&a)[4],
                                         uint32_t b0, uint32_t b1) {
    asm volatile(
        "mma.sync.aligned.m16n8k16.row.col.f32.bf16.bf16.f32 "
        "{%0,%1,%2,%3}, {%4,%5,%6,%7}, {%8,%9}, {%0,%1,%2,%3};"
        : "+f"(c[0]), "+f"(c[1]), "+f"(c[2]), "+f"(c[3])
        : "r"(a[0]), "r"(a[1]), "r"(a[2]), "r"(a[3]), "r"(b0), "r"(b1));
}

// =====================================================================
// K0: W_proj fp32 -> bf16
// =====================================================================
__global__ void convert_wp_kernel(const float* __restrict__ Wp) {
    int idx = blockIdx.x * 256 + threadIdx.x;
    g_wp[idx] = __float2bfloat16(Wp[idx]);
}

// =====================================================================
// K1/K2: C[M,N] = A[M,K] @ W[N,K]^T + bias[N]
// =====================================================================
__global__ void __launch_bounds__(256) gemm_bias_kernel(
    const float* __restrict__ A, const float* __restrict__ W,
    const float* __restrict__ bias, float* __restrict__ C,
    int M, int N, int K)
{
    __shared__ float As[16][64];
    __shared__ float Ws[16][64];
    const int m0 = blockIdx.x * 64;
    const int n0 = blockIdx.y * 64;
    const int tid = threadIdx.x;
    const int tm = tid >> 4, tn = tid & 15;

    float acc[4][4];
#pragma unroll
    for (int i = 0; i < 4; i++)
#pragma unroll
        for (int j = 0; j < 4; j++) acc[i][j] = 0.f;

    for (int k0 = 0; k0 < K; k0 += 16) {
        __syncthreads();
#pragma unroll
        for (int i = 0; i < 4; i++) {
            int q = tid + i * 256;
            int mm = q >> 4, kk = q & 15;
            int gm = m0 + mm;
            As[kk][mm] = (gm < M) ? A[(size_t)gm * K + k0 + kk] : 0.f;
            int gn = n0 + mm;
            Ws[kk][mm] = W[(size_t)gn * K + k0 + kk];
        }
        __syncthreads();
#pragma unroll
        for (int kk = 0; kk < 16; kk++) {
            float a[4], w[4];
#pragma unroll
            for (int i = 0; i < 4; i++) a[i] = As[kk][tm * 4 + i];
#pragma unroll
            for (int j = 0; j < 4; j++) w[j] = Ws[kk][tn * 4 + j];
#pragma unroll
            for (int i = 0; i < 4; i++)
#pragma unroll
                for (int j = 0; j < 4; j++) acc[i][j] = fmaf(a[i], w[j], acc[i][j]);
        }
    }
#pragma unroll
    for (int i = 0; i < 4; i++) {
        int gm = m0 + tm * 4 + i;
        if (gm < M) {
#pragma unroll
            for (int j = 0; j < 4; j++) {
                int gn = n0 + tn * 4 + j;
                C[(size_t)gm * N + gn] = acc[i][j] + bias[gn];
            }
        }
    }
}

// =====================================================================
// K3: mma.sync bf16 joint GEMM + fused log-softmax (warp tile 32x64)
// =====================================================================
__device__ __forceinline__ void load_b_tile(int bt, uint32_t b_base, int tid) {
    uint32_t buf = b_base + (uint32_t)(bt % NBUF) * BT_BYTES;
    const int nc = bt >> 3, ktl = bt & 7;
    const int n = tid >> 1;                 // 256 rows, 2 threads/row
    const int c0 = (tid & 1) * 4;           // 4 x 16B per thread
    const __nv_bfloat16* src = g_wp + ((size_t)(nc * 256 + n) * DJ + ktl * 64 + c0 * 8);
    const uint32_t row = buf + (uint32_t)n * 128u;
    const uint32_t sw = (uint32_t)(n & 7);
#pragma unroll
    for (int j = 0; j < 4; j++) {
        uint32_t c = (uint32_t)(c0 + j);
        cp_async16(row + ((c ^ sw) << 4), src + j * 8);
    }
    asm volatile("cp.async.commit_group;" ::: "memory");
}

__global__ void __launch_bounds__(JTHREADS, 1) joint_kernel(const int* __restrict__ targets)
{
    extern __shared__ __align__(16) char dyn[];
    __shared__ int tgtm[MTILE];

    const uint32_t base = (smem_u32(dyn) + 1023u) & ~1023u;
    const uint32_t a_base = base;
    const uint32_t b_base = base + A_BYTES;

    const int tid  = threadIdx.x;
    const int lane = tid & 31;
    const int wid  = tid >> 5;
    const int warp_m = wid & 3;     // 4 M-warps of 32 rows
    const int warp_n = wid >> 2;    // 4 N-warps of 64 cols (over 256-col chunk)
    const int g0 = blockIdx.x * MTILE;
    const unsigned FM = 0xffffffffu;

    if (tid < MTILE) {
        int g = g0 + tid;
        int b = g / (TT * UP);
        int r = g - b * (TT * UP);
        int u = r % UP;
        tgtm[tid] = (u < UU) ? targets[b * UU + u] : -1;
    }

    // ---- generate h tile into XOR-swizzled A (bf16); each thread 128 k ----
    {
        const int m = tid >> 2;
        const int kq = (tid & 3) * 128;
        int g = g0 + m;
        int b = g / (TT * UP);
        int r = g - b * (TT * UP);
        int t = r / UP, u = r - t * UP;
        const float4* er = reinterpret_cast<const float4*>(
            g_enc_h + ((size_t)(b * TT + t)) * DJ + kq);
        const float4* dr = reinterpret_cast<const float4*>(
            g_dec_h + ((size_t)(b * UP + u)) * DJ + kq);
        const uint32_t mrow = a_base + (uint32_t)m * 1024u;
        const uint32_t msw = (uint32_t)(m & 7);
#pragma unroll 4
        for (int i = 0; i < 16; i++) {
            int k = kq + i * 8;
            float4 e0 = er[i * 2], e1 = er[i * 2 + 1];
            float4 d0 = dr[i * 2], d1 = dr[i * 2 + 1];
            uint32_t p0 = pack_bf16x2(tanh_fast(e0.x * d0.x), tanh_fast(e0.y * d0.y));
            uint32_t p1 = pack_bf16x2(tanh_fast(e0.z * d0.z), tanh_fast(e0.w * d0.w));
            uint32_t p2 = pack_bf16x2(tanh_fast(e1.x * d1.x), tanh_fast(e1.y * d1.y));
            uint32_t p3 = pack_bf16x2(tanh_fast(e1.z * d1.z), tanh_fast(e1.w * d1.w));
            uint32_t c = (uint32_t)(k >> 3);
            uint32_t addr = mrow + ((c ^ msw) << 4);
            asm volatile("st.shared.v4.b32 [%0], {%1,%2,%3,%4};"
                         :: "r"(addr), "r"(p0), "r"(p1), "r"(p2), "r"(p3) : "memory");
        }
    }
    __syncthreads();

    // ---- prologue: prefetch B tiles 0,1 ----
    load_b_tile(0, b_base, tid);
    load_b_tile(1, b_base, tid);

    // ---- per-lane ldmatrix addressing ----
    const int rowA = warp_m * 32 + (lane & 15);
    const uint32_t a_lane = a_base + (uint32_t)rowA * 1024u;
    const uint32_t swzA = (uint32_t)(rowA & 7);
    const uint32_t cbaseA = (uint32_t)(lane >> 4);
    const int n_row_base = warp_n * 64 + ((lane >> 4) << 3) + (lane & 7);
    const uint32_t kh = (uint32_t)((lane >> 3) & 1);
    const uint32_t swzB = (uint32_t)(lane & 7);
    uint32_t rowoffB[4];
#pragma unroll
    for (int p = 0; p < 4; p++) rowoffB[p] = (uint32_t)(n_row_base + p * 16) * 128u;

    // ---- per-row epilogue state ----
    float sm[4], blankv[4], tgtv[4];
    int tg[4];
#pragma unroll
    for (int g = 0; g < 4; g++) {
        sm[g] = 0.f; blankv[g] = 0.f; tgtv[g] = 0.f;
        int m = warp_m * 32 + (g >> 1) * 16 + (g & 1) * 8 + (lane >> 2);
        tg[g] = tgtm[m];
    }

    float acc[2][8][4];

#pragma unroll 1
    for (int bt = 0; bt < NTILES; bt++) {
        const int ktl = bt & 7;
        if (bt < NTILES - 1) asm volatile("cp.async.wait_group 1;" ::: "memory");
        else                 asm volatile("cp.async.wait_group 0;" ::: "memory");
        __syncthreads();
        if (bt + 2 < NTILES) load_b_tile(bt + 2, b_base, tid);

        if (ktl == 0) {
#pragma unroll
            for (int mi = 0; mi < 2; mi++)
#pragma unroll
                for (int nf = 0; nf < 8; nf++)
#pragma unroll
                    for (int j = 0; j < 4; j++) acc[mi][nf][j] = 0.f;
        }

        const uint32_t bbuf = b_base + (uint32_t)(bt % NBUF) * BT_BYTES;
#pragma unroll
        for (int s = 0; s < 4; s++) {
            uint32_t a0[4], a1[4];
            uint32_t cA = (uint32_t)(ktl * 8 + s * 2) + cbaseA;
            uint32_t aaddr = a_lane + ((cA ^ swzA) << 4);
            ldsm_x4(a0, aaddr);
            ldsm_x4(a1, aaddr + 16384u);
            uint32_t b[4][4];
            uint32_t cB = ((uint32_t)(s * 2) + kh) ^ swzB;
#pragma unroll
            for (int p = 0; p < 4; p++)
                ldsm_x4(b[p], bbuf + rowoffB[p] + (cB << 4));
#pragma unroll
            for (int p = 0; p < 4; p++) {
                mma_bf16(acc[0][2 * p],     a0, b[p][0], b[p][1]);
                mma_bf16(acc[0][2 * p + 1], a0, b[p][2], b[p][3]);
                mma_bf16(acc[1][2 * p],     a1, b[p][0], b[p][1]);
                mma_bf16(acc[1][2 * p + 1], a1, b[p][2], b[p][3]);
            }
        }

        if (ktl == 7) {
            const int nc = bt >> 3;
            const int vbase = nc * 256 + warp_n * 64 + (lane & 3) * 2;
#pragma unroll
            for (int g = 0; g < 4; g++) {
                const int mi = g >> 1, hf = (g & 1) * 2;
                float ls = 0.f;
#pragma unroll
                for (int nf = 0; nf < 8; nf++)
                    ls += __expf(acc[mi][nf][hf]) + __expf(acc[mi][nf][hf + 1]);
                ls += __shfl_xor_sync(FM, ls, 1);
                ls += __shfl_xor_sync(FM, ls, 2);
                sm[g] += ls;
#pragma unroll
                for (int nf = 0; nf < 8; nf++) {
                    int v0 = vbase + nf * 8;
                    if (v0 == 0)         blankv[g] = acc[mi][nf][hf];
                    if (v0 == tg[g])     tgtv[g]   = acc[mi][nf][hf];
                    if (v0 + 1 == tg[g]) tgtv[g]   = acc[mi][nf][hf + 1];
                }
            }
        }
    }

    // gather captured values across the 4 lanes of each row group
#pragma unroll
    for (int g = 0; g < 4; g++) {
        tgtv[g]   += __shfl_xor_sync(FM, tgtv[g], 1);
        tgtv[g]   += __shfl_xor_sync(FM, tgtv[g], 2);
        blankv[g] += __shfl_xor_sync(FM, blankv[g], 1);
        blankv[g] += __shfl_xor_sync(FM, blankv[g], 2);
    }

    // reuse B buffer smem for the cross-n-warp combine
    __syncthreads();
    float* ssum   = reinterpret_cast<float*>(dyn) + ((b_base - smem_u32(dyn)) >> 2);
    float* stgtv  = ssum + 4 * MTILE;
    float* sblank = stgtv + 4 * MTILE;

    if ((lane & 3) == 0) {
#pragma unroll
        for (int g = 0; g < 4; g++) {
            int m = warp_m * 32 + (g >> 1) * 16 + (g & 1) * 8 + (lane >> 2);
            ssum[warp_n * MTILE + m]  = sm[g];
            stgtv[warp_n * MTILE + m] = tgtv[g];
            if (warp_n == 0) sblank[m] = blankv[g];
        }
    }
    __syncthreads();

    if (tid < MTILE) {
        int m = tid;
        float lse = __logf(ssum[m] + ssum[MTILE + m] + ssum[2 * MTILE + m] + ssum[3 * MTILE + m]);
        int g = g0 + m;
        int b = g / (TT * UP);
        int r = g - b * (TT * UP);
        int t = r / UP, u = r - t * UP;
        g_blank[g] = sblank[m] - lse;
        if (u < UU) {
            int h = (tgtm[m] >> 6) & 3;   // which 64-col N-warp owns target
            g_emit[(size_t)(b * TT + t) * UU + u] = stgtv[h * MTILE + m] - lse;
        }
    }
}

// =====================================================================
// K4: alpha DP — fused (E,M,S) semiring scan, one warp per batch
// =====================================================================
__global__ void dp_kernel(const int* __restrict__ in_len, const int* __restrict__ tgt_len) {
    const int b = blockIdx.x;
    const int lane = threadIdx.x;
    const float* blank = g_blank + (size_t)b * TT * UP;
    const float* emit  = g_emit  + (size_t)b * TT * UU;
    const int til = in_len[b];
    const int ul  = tgt_len[b];
    const int u0 = lane * 3;
    const unsigned FM = 0xffffffffu;
    const bool a0ok = (u0 < UP), a1ok = (u0 + 1 < UP), a2ok = (u0 + 2 < UP);

    float alpha[3];

    {
        float x0 = (u0 >= 1 && a0ok) ? emit[u0 - 1] : 0.f;
        float x1 = a1ok ? emit[u0] : 0.f;
        float x2 = a2ok ? emit[u0 + 1] : 0.f;
        float s0 = x0, s1 = s0 + x1, s2 = s1 + x2;
        float tot = s2;
#pragma unroll
        for (int o = 1; o < 32; o <<= 1) {
            float n = __shfl_up_sync(FM, tot, o);
            if (lane >= o) tot += n;
        }
        float ex = __shfl_up_sync(FM, tot, 1);
        if (lane == 0) ex = 0.f;
        alpha[0] = ex + s0; alpha[1] = ex + s1; alpha[2] = ex + s2;
    }

    float bl[3], xe[3];
    {
        const float* bp = blank;
        bl[0] = a0ok ? bp[u0] : 0.f;
        bl[1] = a1ok ? bp[u0 + 1] : 0.f;
        bl[2] = a2ok ? bp[u0 + 2] : 0.f;
        const float* ep = emit + UU;
        xe[0] = (u0 >= 1 && a0ok) ? ep[u0 - 1] : 0.f;
        xe[1] = a1ok ? ep[u0] : 0.f;
        xe[2] = a2ok ? ep[u0 + 1] : 0.f;
    }

    for (int t = 1; t < til; t++) {
        float nbl[3], nxe[3];
        if (t + 1 < til) {
            const float* bp = blank + (size_t)t * UP;
            nbl[0] = a0ok ? bp[u0] : 0.f;
            nbl[1] = a1ok ? bp[u0 + 1] : 0.f;
            nbl[2] = a2ok ? bp[u0 + 2] : 0.f;
            const float* ep = emit + (size_t)(t + 1) * UU;
            nxe[0] = (u0 >= 1 && a0ok) ? ep[u0 - 1] : 0.f;
            nxe[1] = a1ok ? ep[u0] : 0.f;
            nxe[2] = a2ok ? ep[u0 + 1] : 0.f;
        }

        float tmp0 = a0ok ? (alpha[0] + bl[0]) : -1e30f;
        float tmp1 = a1ok ? (alpha[1] + bl[1]) : -1e30f;
        float tmp2 = a2ok ? (alpha[2] + bl[2]) : -1e30f;

        float E0 = xe[0], M0 = tmp0, S0 = 1.f;
        float t1 = M0 + xe[1];
        float M1 = fmaxf(t1, tmp1);
        float S1 = S0 * __expf(t1 - M1) + __expf(tmp1 - M1);
        float E1 = E0 + xe[1];
        float t2 = M1 + xe[2];
        float M2 = fmaxf(t2, tmp2);
        float S2 = S1 * __expf(t2 - M2) + __expf(tmp2 - M2);
        float E2 = E1 + xe[2];

        float Ew = E2, Mw = M2, Sw = S2;
#pragma unroll
        for (int o = 1; o < 32; o <<= 1) {
            float Ep = __shfl_up_sync(FM, Ew, o);
            float Mp = __shfl_up_sync(FM, Mw, o);
            float Sp = __shfl_up_sync(FM, Sw, o);
            if (lane >= o) {
                float tt = Mp + Ew;
                float nm = fmaxf(tt, Mw);
                Sw = Sp * __expf(tt - nm) + Sw * __expf(Mw - nm);
                Mw = nm;
                Ew = Ep + Ew;
            }
        }
        float Pe = __shfl_up_sync(FM, Ew, 1);
        float Pm = __shfl_up_sync(FM, Mw, 1);
        float Ps = __shfl_up_sync(FM, Sw, 1);
        if (lane == 0) { Pe = 0.f; Pm = -1e30f; Ps = 0.f; }

        {
            float tt = Pm + E0;
            float nm = fmaxf(tt, M0);
            float S = Ps * __expf(tt - nm) + S0 * __expf(M0 - nm);
            alpha[0] = nm + __logf(S);
        }
        {
            float tt = Pm + E1;
            float nm = fmaxf(tt, M1);
            float S = Ps * __expf(tt - nm) + S1 * __expf(M1 - nm);
            alpha[1] = nm + __logf(S);
        }
        {
            float tt = Pm + E2;
            float nm = fmaxf(tt, M2);
            float S = Ps * __expf(tt - nm) + S2 * __expf(M2 - nm);
            alpha[2] = nm + __logf(S);
        }

        bl[0] = nbl[0]; bl[1] = nbl[1]; bl[2] = nbl[2];
        xe[0] = nxe[0]; xe[1] = nxe[1]; xe[2] = nxe[2];
    }

    int j = ul - u0;
    if (j >= 0 && j < 3) {
        float a = (j == 0) ? alpha[0] : (j == 1) ? alpha[1] : alpha[2];
        g_final[b] = a + blank[(size_t)(til - 1) * UP + ul];
    }
}

__global__ void finalize_kernel(float* out) {
    out[0] = -0.25f * (g_final[0] + g_final[1] + g_final[2] + g_final[3]);
}

// =====================================================================
// launch
// =====================================================================
extern "C" void kernel_launch(void* const* d_in, const int* in_sizes, int n_in,
                              void* d_out, int out_size)
{
    const float* enc     = (const float*)d_in[0];
    const float* dec     = (const float*)d_in[1];
    const int*   targets = (const int*)  d_in[2];
    const int*   in_len  = (const int*)  d_in[3];
    const int*   tgt_len = (const int*)  d_in[4];
    const float* W_enc   = (const float*)d_in[5];
    const float* b_enc   = (const float*)d_in[6];
    const float* W_dec   = (const float*)d_in[7];
    const float* b_dec   = (const float*)d_in[8];
    const float* W_proj  = (const float*)d_in[9];

    void *pe = nullptr, *pd = nullptr;
    cudaGetSymbolAddress(&pe, g_enc_h);
    cudaGetSymbolAddress(&pd, g_dec_h);

    const int smem_joint = 1024 + A_BYTES + NBUF * BT_BYTES;   // 230400 B
    cudaFuncSetAttribute(joint_kernel, cudaFuncAttributeMaxDynamicSharedMemorySize, smem_joint);

    convert_wp_kernel<<<(VV * DJ) / 256, 256>>>(W_proj);

    dim3 g1((BB * TT + 63) / 64, DJ / 64);
    gemm_bias_kernel<<<g1, 256>>>(enc, W_enc, b_enc, (float*)pe, BB * TT, DJ, 512);

    dim3 g2((BB * UP + 63) / 64, DJ / 64);
    gemm_bias_kernel<<<g2, 256>>>(dec, W_dec, b_dec, (float*)pd, BB * UP, DJ, 512);

    joint_kernel<<<(BB * TT * UP) / MTILE, JTHREADS, smem_joint>>>(targets);

    dp_kernel<<<BB, 32>>>(in_len, tgt_len);

    finalize_kernel<<<1, 1>>>((float*)d_out);
}